// round 10
// baseline (speedup 1.0000x reference)
#include <cuda_runtime.h>
#include <cuda_bf16.h>
#include <cuda_fp16.h>
#include <math.h>
#include <cstdint>

#define B_    8
#define SEQ   8192
#define DIM   512
#define HEADS 8
#define HD    64
#define FF_   2048
#define WIN   128
#define TD    512
#define NTOK  (B_*SEQ)        // 65536
#define NW    (SEQ/WIN)       // 64

// ---------------- scratch (device globals; no runtime allocation) ----------
__device__ float g_ss  [B_ * 2 * DIM];
__device__ float g_qkv [(size_t)NTOK * 3 * DIM];   // fp32 qkv
__device__ float g_y   [(size_t)NTOK * DIM];       // x + proj(attn), fp32
// single-fp16 activations (GEMM A operands)
__device__ __half g_xf [(size_t)NTOK * DIM];       // LN1 / LN2 out
__device__ __half g_af [(size_t)NTOK * DIM];       // attention out
__device__ __half g_ff [(size_t)NTOK * FF_];       // gelu out
// weights single fp16, transposed to [N][K] (K contiguous)
__device__ __half g_wq[1536 * 512];
__device__ __half g_wp[512 * 512];
__device__ __half g_w1[2048 * 512];
__device__ __half g_w2[512 * 2048];

// ---------------- PTX helpers ----------------------------------------------
__device__ __forceinline__ uint32_t smem_u32(const void* p) {
    uint32_t a;
    asm("{ .reg .u64 t; cvta.to.shared.u64 t, %1; cvt.u32.u64 %0, t; }"
        : "=r"(a) : "l"(p));
    return a;
}
__device__ __forceinline__ void cp16(uint32_t dst, const void* src) {
    asm volatile("cp.async.cg.shared.global [%0], [%1], 16;"
                 :: "r"(dst), "l"(src) : "memory");
}
#define CP_COMMIT() asm volatile("cp.async.commit_group;" ::: "memory")
#define CP_WAIT(n)  asm volatile("cp.async.wait_group %0;" :: "n"(n) : "memory")

__device__ __forceinline__ void ldsm4(uint32_t* r, uint32_t addr) {
    asm volatile("ldmatrix.sync.aligned.m8n8.x4.shared.b16 {%0,%1,%2,%3}, [%4];"
                 : "=r"(r[0]), "=r"(r[1]), "=r"(r[2]), "=r"(r[3]) : "r"(addr));
}
__device__ __forceinline__ void ldsm4t(uint32_t* r, uint32_t addr) {
    asm volatile("ldmatrix.sync.aligned.m8n8.x4.trans.shared.b16 {%0,%1,%2,%3}, [%4];"
                 : "=r"(r[0]), "=r"(r[1]), "=r"(r[2]), "=r"(r[3]) : "r"(addr));
}
// bf16 mma (attention)
__device__ __forceinline__ void mma_bf(float* d, const uint32_t* a,
                                       const uint32_t* b) {
    asm volatile(
        "mma.sync.aligned.m16n8k16.row.col.f32.bf16.bf16.f32 "
        "{%0,%1,%2,%3}, {%4,%5,%6,%7}, {%8,%9}, {%0,%1,%2,%3};"
        : "+f"(d[0]), "+f"(d[1]), "+f"(d[2]), "+f"(d[3])
        : "r"(a[0]), "r"(a[1]), "r"(a[2]), "r"(a[3]), "r"(b[0]), "r"(b[1]));
}
// fp16 mma (GEMMs)
__device__ __forceinline__ void mma_fp(float* d, const uint32_t* a,
                                       const uint32_t* b) {
    asm volatile(
        "mma.sync.aligned.m16n8k16.row.col.f32.f16.f16.f32 "
        "{%0,%1,%2,%3}, {%4,%5,%6,%7}, {%8,%9}, {%0,%1,%2,%3};"
        : "+f"(d[0]), "+f"(d[1]), "+f"(d[2]), "+f"(d[3])
        : "r"(a[0]), "r"(a[1]), "r"(a[2]), "r"(a[3]), "r"(b[0]), "r"(b[1]));
}
__device__ __forceinline__ uint32_t swz(uint32_t r, uint32_t c16) {
    return (r << 7) + ((c16 ^ (r & 7)) << 4);
}
__device__ __forceinline__ void split_hl_bf(float v, __nv_bfloat16& h, __nv_bfloat16& l) {
    h = __float2bfloat16(v);
    l = __float2bfloat16(v - __bfloat162float(h));
}
__device__ __forceinline__ uint32_t pack_bf2(__nv_bfloat16 a, __nv_bfloat16 b) {
    __nv_bfloat162 p = __halves2bfloat162(a, b);
    return *reinterpret_cast<uint32_t*>(&p);
}
__device__ __forceinline__ uint32_t pack_h2(float a, float b) {
    __half2 p = __floats2half2_rn(a, b);
    return *reinterpret_cast<uint32_t*>(&p);
}

// ---------------- kernel 0: weight transpose -> single fp16 ----------------
__global__ void wprep_kernel(const float* __restrict__ W,
                             __half* __restrict__ oh, int K, int N) {
    __shared__ float tile[32][33];
    int bx = blockIdx.x * 32, by = blockIdx.y * 32;
    int tx = threadIdx.x, ty = threadIdx.y;
    #pragma unroll
    for (int i = 0; i < 4; i++) {
        int k = by + ty + i * 8;
        tile[ty + i * 8][tx] = W[(size_t)k * N + bx + tx];
    }
    __syncthreads();
    #pragma unroll
    for (int i = 0; i < 4; i++) {
        int n = bx + ty + i * 8;
        int k = by + tx;
        oh[(size_t)n * K + k] = __float2half_rn(tile[tx][ty + i * 8]);
    }
}

// ---------------- kernel 1: ss = silu(t_emb) @ time_w + time_b -------------
__global__ void time_mlp_kernel(const float* __restrict__ te,
                                const float* __restrict__ tw,
                                const float* __restrict__ tb) {
    __shared__ float st[TD];
    int b = blockIdx.y;
    for (int k = threadIdx.x; k < TD; k += blockDim.x) {
        float v = te[b * TD + k];
        st[k] = v / (1.f + __expf(-v));
    }
    __syncthreads();
    int j = blockIdx.x * blockDim.x + threadIdx.x;
    float acc = tb[j];
    for (int k = 0; k < TD; k++)
        acc = fmaf(st[k], tw[k * (2 * DIM) + j], acc);
    g_ss[b * 2 * DIM + j] = acc;
}

// ---------------- kernel 2: LayerNorm -> single fp16 -----------------------
template <int MOD>
__global__ void ln_kernel(const float* __restrict__ x,
                          const float* __restrict__ gam,
                          const float* __restrict__ bet,
                          __half* __restrict__ of) {
    int row  = blockIdx.x;
    int t    = threadIdx.x;
    int lane = t & 31, wid = t >> 5;
    float4 xv = ((const float4*)(x + (size_t)row * DIM))[t];
    float s  = xv.x + xv.y + xv.z + xv.w;
    float s2 = fmaf(xv.x, xv.x, fmaf(xv.y, xv.y, fmaf(xv.z, xv.z, xv.w * xv.w)));
    #pragma unroll
    for (int o = 16; o > 0; o >>= 1) {
        s  += __shfl_xor_sync(0xffffffffu, s,  o);
        s2 += __shfl_xor_sync(0xffffffffu, s2, o);
    }
    __shared__ float red[8];
    if (lane == 0) { red[wid] = s; red[4 + wid] = s2; }
    __syncthreads();
    s  = red[0] + red[1] + red[2] + red[3];
    s2 = red[4] + red[5] + red[6] + red[7];
    float mu   = s * (1.f / DIM);
    float var  = s2 * (1.f / DIM) - mu * mu;
    float rstd = rsqrtf(var + 1e-5f);

    float4 gg = ((const float4*)gam)[t];
    float4 bb = ((const float4*)bet)[t];
    float o4[4];
    o4[0] = (xv.x - mu) * rstd * gg.x + bb.x;
    o4[1] = (xv.y - mu) * rstd * gg.y + bb.y;
    o4[2] = (xv.z - mu) * rstd * gg.z + bb.z;
    o4[3] = (xv.w - mu) * rstd * gg.w + bb.w;
    if (MOD) {
        int b = row >> 13;
        float4 sc = ((const float4*)(g_ss + b * 2 * DIM))[t];
        float4 sh = ((const float4*)(g_ss + b * 2 * DIM + DIM))[t];
        o4[0] = o4[0] * (1.f + sc.x) + sh.x;
        o4[1] = o4[1] * (1.f + sc.y) + sh.y;
        o4[2] = o4[2] * (1.f + sc.z) + sh.z;
        o4[3] = o4[3] * (1.f + sc.w) + sh.w;
    }
    ((uint2*)(of + (size_t)row * DIM))[t] =
        make_uint2(pack_h2(o4[0], o4[1]), pack_h2(o4[2], o4[3]));
}

// ---------------- kernel 3: single-fp16 GEMM, K-tile 64, 2-stage -----------
// C[M,N] = A[M,K] @ B[N,K]^T + bias [...]; 1 MMA per k16.
// EPI: 0 = bias -> f32; 1 = bias+res -> f32; 2 = bias+GELU -> fp16
#define KSTEP 64
#define STG   32768
template <int EPI>
__global__ __launch_bounds__(256, 2)
void mma_gemm(const __half* __restrict__ A,
              const __half* __restrict__ B,
              const float* __restrict__ bias,
              const float* __restrict__ res,
              float* __restrict__ Cf,
              __half* __restrict__ Ch,
              int K, int N) {
    extern __shared__ char smem[];
    const uint32_t sbase = smem_u32(smem);
    const int tid = threadIdx.x, w = tid >> 5, lane = tid & 31;
    const int bm = blockIdx.y * 128, bn = blockIdx.x * 128;
    const int warpM = (w >> 2) * 64, warpN = (w & 3) * 32;
    const int T = K / KSTEP;

    const int r_ld = tid >> 3, c_ld = tid & 7;

    auto issue = [&](int t) {
        int k0 = t * KSTEP;
        uint32_t sa = sbase + (t & 1) * STG;
        uint32_t sb = sa + 16384;
        #pragma unroll
        for (int i = 0; i < 4; i++) {
            int r = r_ld + i * 32;
            uint32_t off = swz((uint32_t)r, (uint32_t)c_ld);
            cp16(sa + off, A + (size_t)(bm + r) * K + k0 + c_ld * 8);
            cp16(sb + off, B + (size_t)(bn + r) * K + k0 + c_ld * 8);
        }
        CP_COMMIT();
    };

    float acc[4][4][4];
    #pragma unroll
    for (int i = 0; i < 4; i++)
        #pragma unroll
        for (int j = 0; j < 4; j++)
            #pragma unroll
            for (int e = 0; e < 4; e++) acc[i][j][e] = 0.f;

    const int laA_r = lane & 15, laA_h = lane >> 4;
    const int laB_r = (lane & 7) + ((lane >> 4) << 3);
    const int laB_h = (lane >> 3) & 1;

    issue(0);
    for (int t = 0; t < T; t++) {
        if (t + 1 < T) { issue(t + 1); CP_WAIT(1); }
        else           { CP_WAIT(0); }
        __syncthreads();

        uint32_t sa = sbase + (t & 1) * STG;
        uint32_t sb = sa + 16384;
        #pragma unroll
        for (int i = 0; i < 4; i++) {        // k16 groups within 64-K tile
            uint32_t af[4][4], bf[2][4];
            #pragma unroll
            for (int mi = 0; mi < 4; mi++) {
                uint32_t row = warpM + mi * 16 + laA_r;
                ldsm4(af[mi], sa + swz(row, 2 * i + laA_h));
            }
            #pragma unroll
            for (int nj = 0; nj < 2; nj++) {
                uint32_t row = warpN + nj * 16 + laB_r;
                ldsm4(bf[nj], sb + swz(row, 2 * i + laB_h));
            }
            #pragma unroll
            for (int mi = 0; mi < 4; mi++)
                #pragma unroll
                for (int n8 = 0; n8 < 4; n8++)
                    mma_fp(acc[mi][n8], af[mi], &bf[n8 >> 1][(n8 & 1) * 2]);
        }
        __syncthreads();
    }

    int tr = lane >> 2, tc = (lane & 3) * 2;
    #pragma unroll
    for (int mi = 0; mi < 4; mi++) {
        #pragma unroll
        for (int half = 0; half < 2; half++) {
            int row = bm + warpM + mi * 16 + tr + half * 8;
            size_t rowoff = (size_t)row * N;
            #pragma unroll
            for (int n8 = 0; n8 < 4; n8++) {
                int col = bn + warpN + n8 * 8 + tc;
                float2 bi = *(const float2*)(bias + col);
                float ox = acc[mi][n8][half * 2 + 0] + bi.x;
                float oy = acc[mi][n8][half * 2 + 1] + bi.y;
                if (EPI == 1) {
                    float2 rr = *(const float2*)(res + rowoff + col);
                    ox += rr.x; oy += rr.y;
                }
                if (EPI == 2) {
                    ox = 0.5f * ox * (1.f + erff(ox * 0.70710678118654752f));
                    oy = 0.5f * oy * (1.f + erff(oy * 0.70710678118654752f));
                    *(uint32_t*)(Ch + rowoff + col) = pack_h2(ox, oy);
                } else {
                    *(float2*)(Cf + rowoff + col) = make_float2(ox, oy);
                }
            }
        }
    }
}

// ---------------- kernel 4: local windowed attention via mma.sync ----------
// bf16 3-term internally (reads fp32 qkv); outputs single fp16.
__global__ __launch_bounds__(128)
void attn_mma_kernel(const float* __restrict__ qkv,
                     __half* __restrict__ of) {
    extern __shared__ char smc[];
    const uint32_t sQh = smem_u32(smc);
    const uint32_t sQl = sQh + 16384;
    const uint32_t sKh = sQh + 32768;
    const uint32_t sKl = sQh + 49152;
    const uint32_t sVh = sQh + 65536;
    const uint32_t sVl = sQh + 81920;

    const int w = blockIdx.x, h = blockIdx.y, b = blockIdx.z;
    const int tid = threadIdx.x, lane = tid & 31;
    const int warpM = (tid >> 5) * 32;

    const int laA_r = lane & 15, laA_h = lane >> 4;
    const int laB_r = (lane & 7) + ((lane >> 4) << 3);
    const int laB_h = (lane >> 3) & 1;

    // ---- load Q (x 0.125) -> hi/lo smem (thread = query row) ----
    {
        const float* qp = qkv + (size_t)(b * SEQ + w * WIN + tid) * (3 * DIM) + h * HD;
        #pragma unroll
        for (int c = 0; c < 8; c++) {
            float4 v0 = ((const float4*)qp)[c * 2];
            float4 v1 = ((const float4*)qp)[c * 2 + 1];
            float f[8] = {v0.x, v0.y, v0.z, v0.w, v1.x, v1.y, v1.z, v1.w};
            uint32_t hp[4], lp[4];
            #pragma unroll
            for (int e = 0; e < 4; e++) {
                __nv_bfloat16 h0, l0, h1, l1;
                split_hl_bf(f[2 * e] * 0.125f, h0, l0);
                split_hl_bf(f[2 * e + 1] * 0.125f, h1, l1);
                hp[e] = pack_bf2(h0, h1);
                lp[e] = pack_bf2(l0, l1);
            }
            uint32_t off = swz((uint32_t)tid, (uint32_t)c);
            *(uint4*)(smc + off)         = make_uint4(hp[0], hp[1], hp[2], hp[3]);
            *(uint4*)(smc + 16384 + off) = make_uint4(lp[0], lp[1], lp[2], lp[3]);
        }
    }

    float O[2][8][4];
    #pragma unroll
    for (int mt = 0; mt < 2; mt++)
        #pragma unroll
        for (int n8 = 0; n8 < 8; n8++)
            #pragma unroll
            for (int e = 0; e < 4; e++) O[mt][n8][e] = 0.f;
    float mS[2][2] = {{-1e30f, -1e30f}, {-1e30f, -1e30f}};
    float lS[2][2] = {{0.f, 0.f}, {0.f, 0.f}};

    for (int dw = -1; dw <= 1; dw++) {
        int wi = w + dw;
        if (wi < 0 || wi >= NW) continue;
        __syncthreads();
        // ---- load K,V window -> hi/lo smem (thread = key row) ----
        {
            const float* kp = qkv + (size_t)(b * SEQ + wi * WIN + tid) * (3 * DIM) + DIM + h * HD;
            const float* vp = kp + DIM;
            #pragma unroll
            for (int c = 0; c < 8; c++) {
                float4 k0 = ((const float4*)kp)[c * 2];
                float4 k1 = ((const float4*)kp)[c * 2 + 1];
                float4 u0 = ((const float4*)vp)[c * 2];
                float4 u1 = ((const float4*)vp)[c * 2 + 1];
                float fk[8] = {k0.x, k0.y, k0.z, k0.w, k1.x, k1.y, k1.z, k1.w};
                float fv[8] = {u0.x, u0.y, u0.z, u0.w, u1.x, u1.y, u1.z, u1.w};
                uint32_t kh[4], kl[4], vh[4], vl[4];
                #pragma unroll
                for (int e = 0; e < 4; e++) {
                    __nv_bfloat16 a0, b0, a1, b1;
                    split_hl_bf(fk[2 * e], a0, b0); split_hl_bf(fk[2 * e + 1], a1, b1);
                    kh[e] = pack_bf2(a0, a1); kl[e] = pack_bf2(b0, b1);
                    split_hl_bf(fv[2 * e], a0, b0); split_hl_bf(fv[2 * e + 1], a1, b1);
                    vh[e] = pack_bf2(a0, a1); vl[e] = pack_bf2(b0, b1);
                }
                uint32_t off = swz((uint32_t)tid, (uint32_t)c);
                *(uint4*)(smc + 32768 + off) = make_uint4(kh[0], kh[1], kh[2], kh[3]);
                *(uint4*)(smc + 49152 + off) = make_uint4(kl[0], kl[1], kl[2], kl[3]);
                *(uint4*)(smc + 65536 + off) = make_uint4(vh[0], vh[1], vh[2], vh[3]);
                *(uint4*)(smc + 81920 + off) = make_uint4(vl[0], vl[1], vl[2], vl[3]);
            }
        }
        __syncthreads();

        #pragma unroll
        for (int c0 = 0; c0 < 128; c0 += 64) {
            float S[2][8][4];
            #pragma unroll
            for (int mt = 0; mt < 2; mt++)
                #pragma unroll
                for (int n8 = 0; n8 < 8; n8++)
                    #pragma unroll
                    for (int e = 0; e < 4; e++) S[mt][n8][e] = 0.f;

            #pragma unroll
            for (int kb = 0; kb < 4; kb++) {
                uint32_t aqh[2][4], aql[2][4], bkh[4][4], bkl[4][4];
                #pragma unroll
                for (int mt = 0; mt < 2; mt++) {
                    uint32_t row = warpM + mt * 16 + laA_r;
                    ldsm4(aqh[mt], sQh + swz(row, kb * 2 + laA_h));
                    ldsm4(aql[mt], sQl + swz(row, kb * 2 + laA_h));
                }
                #pragma unroll
                for (int np = 0; np < 4; np++) {
                    uint32_t row = c0 + np * 16 + laB_r;
                    ldsm4(bkh[np], sKh + swz(row, kb * 2 + laB_h));
                    ldsm4(bkl[np], sKl + swz(row, kb * 2 + laB_h));
                }
                #pragma unroll
                for (int mt = 0; mt < 2; mt++)
                    #pragma unroll
                    for (int n8 = 0; n8 < 8; n8++) {
                        const uint32_t* bh2 = &bkh[n8 >> 1][(n8 & 1) * 2];
                        const uint32_t* bl2 = &bkl[n8 >> 1][(n8 & 1) * 2];
                        mma_bf(S[mt][n8], aqh[mt], bh2);
                        mma_bf(S[mt][n8], aqh[mt], bl2);
                        mma_bf(S[mt][n8], aql[mt], bh2);
                    }
            }

            #pragma unroll
            for (int mt = 0; mt < 2; mt++) {
                #pragma unroll
                for (int half = 0; half < 2; half++) {
                    float cm = -1e30f;
                    #pragma unroll
                    for (int n8 = 0; n8 < 8; n8++) {
                        cm = fmaxf(cm, S[mt][n8][half * 2 + 0]);
                        cm = fmaxf(cm, S[mt][n8][half * 2 + 1]);
                    }
                    cm = fmaxf(cm, __shfl_xor_sync(0xffffffffu, cm, 1));
                    cm = fmaxf(cm, __shfl_xor_sync(0xffffffffu, cm, 2));
                    float mn = fmaxf(mS[mt][half], cm);
                    float corr = __expf(mS[mt][half] - mn);
                    float rs = 0.f;
                    #pragma unroll
                    for (int n8 = 0; n8 < 8; n8++) {
                        float p0 = __expf(S[mt][n8][half * 2 + 0] - mn);
                        float p1 = __expf(S[mt][n8][half * 2 + 1] - mn);
                        S[mt][n8][half * 2 + 0] = p0;
                        S[mt][n8][half * 2 + 1] = p1;
                        rs += p0 + p1;
                    }
                    rs += __shfl_xor_sync(0xffffffffu, rs, 1);
                    rs += __shfl_xor_sync(0xffffffffu, rs, 2);
                    lS[mt][half] = lS[mt][half] * corr + rs;
                    mS[mt][half] = mn;
                    #pragma unroll
                    for (int n8 = 0; n8 < 8; n8++) {
                        O[mt][n8][half * 2 + 0] *= corr;
                        O[mt][n8][half * 2 + 1] *= corr;
                    }
                }
            }

            #pragma unroll
            for (int kb = 0; kb < 4; kb++) {
                uint32_t ph[2][4], pl[2][4];
                #pragma unroll
                for (int mt = 0; mt < 2; mt++) {
                    #pragma unroll
                    for (int i = 0; i < 4; i++) {
                        int j = 2 * kb + (i >> 1);
                        float p0 = S[mt][j][(i & 1) * 2 + 0];
                        float p1 = S[mt][j][(i & 1) * 2 + 1];
                        __nv_bfloat16 h0 = __float2bfloat16(p0);
                        __nv_bfloat16 h1 = __float2bfloat16(p1);
                        ph[mt][i] = pack_bf2(h0, h1);
                        pl[mt][i] = pack_bf2(
                            __float2bfloat16(p0 - __bfloat162float(h0)),
                            __float2bfloat16(p1 - __bfloat162float(h1)));
                    }
                }
                uint32_t vfh[4][4], vfl[4][4];
                #pragma unroll
                for (int np = 0; np < 4; np++) {
                    uint32_t row = c0 + kb * 16 + (lane & 15);
                    uint32_t ch = np * 2 + (lane >> 4);
                    ldsm4t(vfh[np], sVh + swz(row, ch));
                    ldsm4t(vfl[np], sVl + swz(row, ch));
                }
                #pragma unroll
                for (int mt = 0; mt < 2; mt++)
                    #pragma unroll
                    for (int n8 = 0; n8 < 8; n8++) {
                        const uint32_t* vh2 = &vfh[n8 >> 1][(n8 & 1) * 2];
                        const uint32_t* vl2 = &vfl[n8 >> 1][(n8 & 1) * 2];
                        mma_bf(O[mt][n8], ph[mt], vh2);
                        mma_bf(O[mt][n8], ph[mt], vl2);
                        mma_bf(O[mt][n8], pl[mt], vh2);
                    }
            }
        }
    }

    #pragma unroll
    for (int mt = 0; mt < 2; mt++) {
        #pragma unroll
        for (int half = 0; half < 2; half++) {
            float inv = 1.f / lS[mt][half];
            int row = warpM + mt * 16 + (lane >> 2) + half * 8;
            size_t base = (size_t)(b * SEQ + w * WIN + row) * DIM + h * HD;
            #pragma unroll
            for (int n8 = 0; n8 < 8; n8++) {
                int col = n8 * 8 + (lane & 3) * 2;
                float x0 = O[mt][n8][half * 2 + 0] * inv;
                float x1 = O[mt][n8][half * 2 + 1] * inv;
                *(uint32_t*)(of + base + col) = pack_h2(x0, x1);
            }
        }
    }
}

// ---------------- host orchestration ---------------------------------------
extern "C" void kernel_launch(void* const* d_in, const int* in_sizes, int n_in,
                              void* d_out, int out_size) {
    const float* x      = (const float*)d_in[0];
    const float* t_emb  = (const float*)d_in[1];
    const float* ln1_g  = (const float*)d_in[2];
    const float* ln1_b  = (const float*)d_in[3];
    const float* qkv_w  = (const float*)d_in[4];
    const float* qkv_b  = (const float*)d_in[5];
    const float* proj_w = (const float*)d_in[6];
    const float* proj_b = (const float*)d_in[7];
    const float* ln2_g  = (const float*)d_in[8];
    const float* ln2_b  = (const float*)d_in[9];
    const float* mlp_w1 = (const float*)d_in[10];
    const float* mlp_b1 = (const float*)d_in[11];
    const float* mlp_w2 = (const float*)d_in[12];
    const float* mlp_b2 = (const float*)d_in[13];
    const float* time_w = (const float*)d_in[14];
    const float* time_b = (const float*)d_in[15];
    float* out = (float*)d_out;

    void* p;
    float *qkv, *y;
    __half *xf, *af, *ff;
    __half *wq, *wp, *w1, *w2;
    cudaGetSymbolAddress(&p, g_qkv);  qkv = (float*)p;
    cudaGetSymbolAddress(&p, g_y);    y   = (float*)p;
    cudaGetSymbolAddress(&p, g_xf);   xf  = (__half*)p;
    cudaGetSymbolAddress(&p, g_af);   af  = (__half*)p;
    cudaGetSymbolAddress(&p, g_ff);   ff  = (__half*)p;
    cudaGetSymbolAddress(&p, g_wq);   wq  = (__half*)p;
    cudaGetSymbolAddress(&p, g_wp);   wp  = (__half*)p;
    cudaGetSymbolAddress(&p, g_w1);   w1  = (__half*)p;
    cudaGetSymbolAddress(&p, g_w2);   w2  = (__half*)p;

    const int gemm_smem = 2 * STG;   // 64 KB
    cudaFuncSetAttribute(mma_gemm<0>, cudaFuncAttributeMaxDynamicSharedMemorySize, gemm_smem);
    cudaFuncSetAttribute(mma_gemm<1>, cudaFuncAttributeMaxDynamicSharedMemorySize, gemm_smem);
    cudaFuncSetAttribute(mma_gemm<2>, cudaFuncAttributeMaxDynamicSharedMemorySize, gemm_smem);
    const int attn_smem = 98304;
    cudaFuncSetAttribute(attn_mma_kernel, cudaFuncAttributeMaxDynamicSharedMemorySize, attn_smem);

    // 0. weight prep (transpose -> fp16)
    wprep_kernel<<<dim3(1536 / 32, 512 / 32), dim3(32, 8)>>>(qkv_w,  wq, 512, 1536);
    wprep_kernel<<<dim3(512 / 32,  512 / 32), dim3(32, 8)>>>(proj_w, wp, 512, 512);
    wprep_kernel<<<dim3(2048 / 32, 512 / 32), dim3(32, 8)>>>(mlp_w1, w1, 512, 2048);
    wprep_kernel<<<dim3(512 / 32, 2048 / 32), dim3(32, 8)>>>(mlp_w2, w2, 2048, 512);
    // 1. adaLN scale/shift
    time_mlp_kernel<<<dim3(2 * DIM / 256, B_), 256>>>(t_emb, time_w, time_b);
    // 2. modulated LN1 -> fp16
    ln_kernel<1><<<NTOK, 128>>>(x, ln1_g, ln1_b, xf);
    // 3. QKV GEMM -> fp32 qkv
    mma_gemm<0><<<dim3(12, NTOK / 128), 256, gemm_smem>>>(
        xf, wq, qkv_b, nullptr, qkv, nullptr, 512, 1536);
    // 4. local attention -> fp16
    attn_mma_kernel<<<dim3(NW, HEADS, B_), 128, attn_smem>>>(qkv, af);
    // 5. proj + residual(x) -> fp32 y
    mma_gemm<1><<<dim3(4, NTOK / 128), 256, gemm_smem>>>(
        af, wp, proj_b, x, y, nullptr, 512, 512);
    // 6. LN2 -> fp16
    ln_kernel<0><<<NTOK, 128>>>(y, ln2_g, ln2_b, xf);
    // 7. MLP up + GELU -> fp16
    mma_gemm<2><<<dim3(16, NTOK / 128), 256, gemm_smem>>>(
        xf, w1, mlp_b1, nullptr, nullptr, ff, 512, 2048);
    // 8. MLP down + residual(y) -> out
    mma_gemm<1><<<dim3(4, NTOK / 128), 256, gemm_smem>>>(
        ff, w2, mlp_b2, y, out, nullptr, 2048, 512);
}

// round 12
// speedup vs baseline: 1.5233x; 1.5233x over previous
#include <cuda_runtime.h>
#include <cuda_bf16.h>
#include <cuda_fp16.h>
#include <math.h>
#include <cstdint>

#define B_    8
#define SEQ   8192
#define DIM   512
#define HEADS 8
#define HD    64
#define FF_   2048
#define WIN   128
#define TD    512
#define NTOK  (B_*SEQ)        // 65536
#define NW    (SEQ/WIN)       // 64

// ---------------- scratch (device globals; no runtime allocation) ----------
__device__ float g_ss  [B_ * 2 * DIM];
__device__ float g_qkv [(size_t)NTOK * 3 * DIM];   // fp32 qkv
__device__ float g_y   [(size_t)NTOK * DIM];       // x + proj(attn), fp32
// single-fp16 activations (GEMM A operands)
__device__ __half g_xf [(size_t)NTOK * DIM];       // LN1 / LN2 out
__device__ __half g_af [(size_t)NTOK * DIM];       // attention out
__device__ __half g_ff [(size_t)NTOK * FF_];       // gelu out
// weights single fp16, transposed to [N][K] (K contiguous)
__device__ __half g_wq[1536 * 512];
__device__ __half g_wp[512 * 512];
__device__ __half g_w1[2048 * 512];
__device__ __half g_w2[512 * 2048];

// ---------------- PTX helpers ----------------------------------------------
__device__ __forceinline__ uint32_t smem_u32(const void* p) {
    uint32_t a;
    asm("{ .reg .u64 t; cvta.to.shared.u64 t, %1; cvt.u32.u64 %0, t; }"
        : "=r"(a) : "l"(p));
    return a;
}
__device__ __forceinline__ void cp16(uint32_t dst, const void* src) {
    asm volatile("cp.async.cg.shared.global [%0], [%1], 16;"
                 :: "r"(dst), "l"(src) : "memory");
}
#define CP_COMMIT() asm volatile("cp.async.commit_group;" ::: "memory")
#define CP_WAIT(n)  asm volatile("cp.async.wait_group %0;" :: "n"(n) : "memory")

__device__ __forceinline__ void ldsm4(uint32_t* r, uint32_t addr) {
    asm volatile("ldmatrix.sync.aligned.m8n8.x4.shared.b16 {%0,%1,%2,%3}, [%4];"
                 : "=r"(r[0]), "=r"(r[1]), "=r"(r[2]), "=r"(r[3]) : "r"(addr));
}
__device__ __forceinline__ void ldsm4t(uint32_t* r, uint32_t addr) {
    asm volatile("ldmatrix.sync.aligned.m8n8.x4.trans.shared.b16 {%0,%1,%2,%3}, [%4];"
                 : "=r"(r[0]), "=r"(r[1]), "=r"(r[2]), "=r"(r[3]) : "r"(addr));
}
// bf16 mma (attention)
__device__ __forceinline__ void mma_bf(float* d, const uint32_t* a,
                                       const uint32_t* b) {
    asm volatile(
        "mma.sync.aligned.m16n8k16.row.col.f32.bf16.bf16.f32 "
        "{%0,%1,%2,%3}, {%4,%5,%6,%7}, {%8,%9}, {%0,%1,%2,%3};"
        : "+f"(d[0]), "+f"(d[1]), "+f"(d[2]), "+f"(d[3])
        : "r"(a[0]), "r"(a[1]), "r"(a[2]), "r"(a[3]), "r"(b[0]), "r"(b[1]));
}
// fp16 mma (GEMMs)
__device__ __forceinline__ void mma_fp(float* d, const uint32_t* a,
                                       const uint32_t* b) {
    asm volatile(
        "mma.sync.aligned.m16n8k16.row.col.f32.f16.f16.f32 "
        "{%0,%1,%2,%3}, {%4,%5,%6,%7}, {%8,%9}, {%0,%1,%2,%3};"
        : "+f"(d[0]), "+f"(d[1]), "+f"(d[2]), "+f"(d[3])
        : "r"(a[0]), "r"(a[1]), "r"(a[2]), "r"(a[3]), "r"(b[0]), "r"(b[1]));
}
__device__ __forceinline__ uint32_t swz(uint32_t r, uint32_t c16) {
    return (r << 7) + ((c16 ^ (r & 7)) << 4);
}
__device__ __forceinline__ void split_hl_bf(float v, __nv_bfloat16& h, __nv_bfloat16& l) {
    h = __float2bfloat16(v);
    l = __float2bfloat16(v - __bfloat162float(h));
}
__device__ __forceinline__ uint32_t pack_bf2(__nv_bfloat16 a, __nv_bfloat16 b) {
    __nv_bfloat162 p = __halves2bfloat162(a, b);
    return *reinterpret_cast<uint32_t*>(&p);
}
__device__ __forceinline__ uint32_t pack_h2(float a, float b) {
    __half2 p = __floats2half2_rn(a, b);
    return *reinterpret_cast<uint32_t*>(&p);
}

// ---------------- kernel 0: weight transpose -> single fp16 ----------------
__global__ void wprep_kernel(const float* __restrict__ W,
                             __half* __restrict__ oh, int K, int N) {
    __shared__ float tile[32][33];
    int bx = blockIdx.x * 32, by = blockIdx.y * 32;
    int tx = threadIdx.x, ty = threadIdx.y;
    #pragma unroll
    for (int i = 0; i < 4; i++) {
        int k = by + ty + i * 8;
        tile[ty + i * 8][tx] = W[(size_t)k * N + bx + tx];
    }
    __syncthreads();
    #pragma unroll
    for (int i = 0; i < 4; i++) {
        int n = bx + ty + i * 8;
        int k = by + tx;
        oh[(size_t)n * K + k] = __float2half_rn(tile[tx][ty + i * 8]);
    }
}

// ---------------- kernel 1: ss = silu(t_emb) @ time_w + time_b -------------
__global__ void time_mlp_kernel(const float* __restrict__ te,
                                const float* __restrict__ tw,
                                const float* __restrict__ tb) {
    __shared__ float st[TD];
    int b = blockIdx.y;
    for (int k = threadIdx.x; k < TD; k += blockDim.x) {
        float v = te[b * TD + k];
        st[k] = v / (1.f + __expf(-v));
    }
    __syncthreads();
    int j = blockIdx.x * blockDim.x + threadIdx.x;
    float acc = tb[j];
    for (int k = 0; k < TD; k++)
        acc = fmaf(st[k], tw[k * (2 * DIM) + j], acc);
    g_ss[b * 2 * DIM + j] = acc;
}

// ---------------- kernel 2: LayerNorm -> single fp16 -----------------------
template <int MOD>
__global__ void ln_kernel(const float* __restrict__ x,
                          const float* __restrict__ gam,
                          const float* __restrict__ bet,
                          __half* __restrict__ of) {
    int row  = blockIdx.x;
    int t    = threadIdx.x;
    int lane = t & 31, wid = t >> 5;
    float4 xv = ((const float4*)(x + (size_t)row * DIM))[t];
    float s  = xv.x + xv.y + xv.z + xv.w;
    float s2 = fmaf(xv.x, xv.x, fmaf(xv.y, xv.y, fmaf(xv.z, xv.z, xv.w * xv.w)));
    #pragma unroll
    for (int o = 16; o > 0; o >>= 1) {
        s  += __shfl_xor_sync(0xffffffffu, s,  o);
        s2 += __shfl_xor_sync(0xffffffffu, s2, o);
    }
    __shared__ float red[8];
    if (lane == 0) { red[wid] = s; red[4 + wid] = s2; }
    __syncthreads();
    s  = red[0] + red[1] + red[2] + red[3];
    s2 = red[4] + red[5] + red[6] + red[7];
    float mu   = s * (1.f / DIM);
    float var  = s2 * (1.f / DIM) - mu * mu;
    float rstd = rsqrtf(var + 1e-5f);

    float4 gg = ((const float4*)gam)[t];
    float4 bb = ((const float4*)bet)[t];
    float o4[4];
    o4[0] = (xv.x - mu) * rstd * gg.x + bb.x;
    o4[1] = (xv.y - mu) * rstd * gg.y + bb.y;
    o4[2] = (xv.z - mu) * rstd * gg.z + bb.z;
    o4[3] = (xv.w - mu) * rstd * gg.w + bb.w;
    if (MOD) {
        int b = row >> 13;
        float4 sc = ((const float4*)(g_ss + b * 2 * DIM))[t];
        float4 sh = ((const float4*)(g_ss + b * 2 * DIM + DIM))[t];
        o4[0] = o4[0] * (1.f + sc.x) + sh.x;
        o4[1] = o4[1] * (1.f + sc.y) + sh.y;
        o4[2] = o4[2] * (1.f + sc.z) + sh.z;
        o4[3] = o4[3] * (1.f + sc.w) + sh.w;
    }
    ((uint2*)(of + (size_t)row * DIM))[t] =
        make_uint2(pack_h2(o4[0], o4[1]), pack_h2(o4[2], o4[3]));
}

// ---------------- kernel 3: single-fp16 GEMM, 3-stage pipeline -------------
// C[M,N] = A[M,K] @ B[N,K]^T + bias [...]; 1 MMA per k16.
// 3-stage cp.async: 2 loads always in flight; ONE sync per K-iter; loads
// for stage t+2 issued BEFORE compute of stage t.
// EPI: 0 = bias -> f32; 1 = bias+res -> f32; 2 = bias+GELU -> fp16
#define KSTEP 64
#define STG   32768
template <int EPI>
__global__ __launch_bounds__(256, 2)
void mma_gemm(const __half* __restrict__ A,
              const __half* __restrict__ B,
              const float* __restrict__ bias,
              const float* __restrict__ res,
              float* __restrict__ Cf,
              __half* __restrict__ Ch,
              int K, int N) {
    extern __shared__ char smem[];
    const uint32_t sbase = smem_u32(smem);
    const int tid = threadIdx.x, w = tid >> 5, lane = tid & 31;
    const int bm = blockIdx.y * 128, bn = blockIdx.x * 128;
    const int warpM = (w >> 2) * 64, warpN = (w & 3) * 32;
    const int T = K / KSTEP;

    const int r_ld = tid >> 3, c_ld = tid & 7;

    auto issue = [&](int t) {
        int k0 = t * KSTEP;
        uint32_t sa = sbase + (t % 3) * STG;
        uint32_t sb = sa + 16384;
        #pragma unroll
        for (int i = 0; i < 4; i++) {
            int r = r_ld + i * 32;
            uint32_t off = swz((uint32_t)r, (uint32_t)c_ld);
            cp16(sa + off, A + (size_t)(bm + r) * K + k0 + c_ld * 8);
            cp16(sb + off, B + (size_t)(bn + r) * K + k0 + c_ld * 8);
        }
        CP_COMMIT();
    };

    float acc[4][4][4];
    #pragma unroll
    for (int i = 0; i < 4; i++)
        #pragma unroll
        for (int j = 0; j < 4; j++)
            #pragma unroll
            for (int e = 0; e < 4; e++) acc[i][j][e] = 0.f;

    const int laA_r = lane & 15, laA_h = lane >> 4;
    const int laB_r = (lane & 7) + ((lane >> 4) << 3);
    const int laB_h = (lane >> 3) & 1;

    issue(0);
    issue(1);
    for (int t = 0; t < T; t++) {
        if (t < T - 1) { CP_WAIT(1); } else { CP_WAIT(0); }
        __syncthreads();
        if (t + 2 < T) issue(t + 2);    // into stage (t-1)%3: safe post-barrier

        uint32_t sa = sbase + (t % 3) * STG;
        uint32_t sb = sa + 16384;
        #pragma unroll
        for (int i = 0; i < 4; i++) {        // k16 groups within 64-K tile
            uint32_t af[4][4], bf[2][4];
            #pragma unroll
            for (int mi = 0; mi < 4; mi++) {
                uint32_t row = warpM + mi * 16 + laA_r;
                ldsm4(af[mi], sa + swz(row, 2 * i + laA_h));
            }
            #pragma unroll
            for (int nj = 0; nj < 2; nj++) {
                uint32_t row = warpN + nj * 16 + laB_r;
                ldsm4(bf[nj], sb + swz(row, 2 * i + laB_h));
            }
            #pragma unroll
            for (int mi = 0; mi < 4; mi++)
                #pragma unroll
                for (int n8 = 0; n8 < 4; n8++)
                    mma_fp(acc[mi][n8], af[mi], &bf[n8 >> 1][(n8 & 1) * 2]);
        }
    }

    int tr = lane >> 2, tc = (lane & 3) * 2;
    #pragma unroll
    for (int mi = 0; mi < 4; mi++) {
        #pragma unroll
        for (int half = 0; half < 2; half++) {
            int row = bm + warpM + mi * 16 + tr + half * 8;
            size_t rowoff = (size_t)row * N;
            #pragma unroll
            for (int n8 = 0; n8 < 4; n8++) {
                int col = bn + warpN + n8 * 8 + tc;
                float2 bi = *(const float2*)(bias + col);
                float ox = acc[mi][n8][half * 2 + 0] + bi.x;
                float oy = acc[mi][n8][half * 2 + 1] + bi.y;
                if (EPI == 1) {
                    float2 rr = *(const float2*)(res + rowoff + col);
                    ox += rr.x; oy += rr.y;
                }
                if (EPI == 2) {
                    ox = 0.5f * ox * (1.f + erff(ox * 0.70710678118654752f));
                    oy = 0.5f * oy * (1.f + erff(oy * 0.70710678118654752f));
                    *(uint32_t*)(Ch + rowoff + col) = pack_h2(ox, oy);
                } else {
                    *(float2*)(Cf + rowoff + col) = make_float2(ox, oy);
                }
            }
        }
    }
}

// ---------------- kernel 4: local windowed attention via mma.sync ----------
// bf16 3-term internally (reads fp32 qkv); outputs single fp16.
__global__ __launch_bounds__(128)
void attn_mma_kernel(const float* __restrict__ qkv,
                     __half* __restrict__ of) {
    extern __shared__ char smc[];
    const uint32_t sQh = smem_u32(smc);
    const uint32_t sQl = sQh + 16384;
    const uint32_t sKh = sQh + 32768;
    const uint32_t sKl = sQh + 49152;
    const uint32_t sVh = sQh + 65536;
    const uint32_t sVl = sQh + 81920;

    const int w = blockIdx.x, h = blockIdx.y, b = blockIdx.z;
    const int tid = threadIdx.x, lane = tid & 31;
    const int warpM = (tid >> 5) * 32;

    const int laA_r = lane & 15, laA_h = lane >> 4;
    const int laB_r = (lane & 7) + ((lane >> 4) << 3);
    const int laB_h = (lane >> 3) & 1;

    // ---- load Q (x 0.125) -> hi/lo smem (thread = query row) ----
    {
        const float* qp = qkv + (size_t)(b * SEQ + w * WIN + tid) * (3 * DIM) + h * HD;
        #pragma unroll
        for (int c = 0; c < 8; c++) {
            float4 v0 = ((const float4*)qp)[c * 2];
            float4 v1 = ((const float4*)qp)[c * 2 + 1];
            float f[8] = {v0.x, v0.y, v0.z, v0.w, v1.x, v1.y, v1.z, v1.w};
            uint32_t hp[4], lp[4];
            #pragma unroll
            for (int e = 0; e < 4; e++) {
                __nv_bfloat16 h0, l0, h1, l1;
                split_hl_bf(f[2 * e] * 0.125f, h0, l0);
                split_hl_bf(f[2 * e + 1] * 0.125f, h1, l1);
                hp[e] = pack_bf2(h0, h1);
                lp[e] = pack_bf2(l0, l1);
            }
            uint32_t off = swz((uint32_t)tid, (uint32_t)c);
            *(uint4*)(smc + off)         = make_uint4(hp[0], hp[1], hp[2], hp[3]);
            *(uint4*)(smc + 16384 + off) = make_uint4(lp[0], lp[1], lp[2], lp[3]);
        }
    }

    float O[2][8][4];
    #pragma unroll
    for (int mt = 0; mt < 2; mt++)
        #pragma unroll
        for (int n8 = 0; n8 < 8; n8++)
            #pragma unroll
            for (int e = 0; e < 4; e++) O[mt][n8][e] = 0.f;
    float mS[2][2] = {{-1e30f, -1e30f}, {-1e30f, -1e30f}};
    float lS[2][2] = {{0.f, 0.f}, {0.f, 0.f}};

    for (int dw = -1; dw <= 1; dw++) {
        int wi = w + dw;
        if (wi < 0 || wi >= NW) continue;
        __syncthreads();
        // ---- load K,V window -> hi/lo smem (thread = key row) ----
        {
            const float* kp = qkv + (size_t)(b * SEQ + wi * WIN + tid) * (3 * DIM) + DIM + h * HD;
            const float* vp = kp + DIM;
            #pragma unroll
            for (int c = 0; c < 8; c++) {
                float4 k0 = ((const float4*)kp)[c * 2];
                float4 k1 = ((const float4*)kp)[c * 2 + 1];
                float4 u0 = ((const float4*)vp)[c * 2];
                float4 u1 = ((const float4*)vp)[c * 2 + 1];
                float fk[8] = {k0.x, k0.y, k0.z, k0.w, k1.x, k1.y, k1.z, k1.w};
                float fv[8] = {u0.x, u0.y, u0.z, u0.w, u1.x, u1.y, u1.z, u1.w};
                uint32_t kh[4], kl[4], vh[4], vl[4];
                #pragma unroll
                for (int e = 0; e < 4; e++) {
                    __nv_bfloat16 a0, b0, a1, b1;
                    split_hl_bf(fk[2 * e], a0, b0); split_hl_bf(fk[2 * e + 1], a1, b1);
                    kh[e] = pack_bf2(a0, a1); kl[e] = pack_bf2(b0, b1);
                    split_hl_bf(fv[2 * e], a0, b0); split_hl_bf(fv[2 * e + 1], a1, b1);
                    vh[e] = pack_bf2(a0, a1); vl[e] = pack_bf2(b0, b1);
                }
                uint32_t off = swz((uint32_t)tid, (uint32_t)c);
                *(uint4*)(smc + 32768 + off) = make_uint4(kh[0], kh[1], kh[2], kh[3]);
                *(uint4*)(smc + 49152 + off) = make_uint4(kl[0], kl[1], kl[2], kl[3]);
                *(uint4*)(smc + 65536 + off) = make_uint4(vh[0], vh[1], vh[2], vh[3]);
                *(uint4*)(smc + 81920 + off) = make_uint4(vl[0], vl[1], vl[2], vl[3]);
            }
        }
        __syncthreads();

        #pragma unroll
        for (int c0 = 0; c0 < 128; c0 += 64) {
            float S[2][8][4];
            #pragma unroll
            for (int mt = 0; mt < 2; mt++)
                #pragma unroll
                for (int n8 = 0; n8 < 8; n8++)
                    #pragma unroll
                    for (int e = 0; e < 4; e++) S[mt][n8][e] = 0.f;

            #pragma unroll
            for (int kb = 0; kb < 4; kb++) {
                uint32_t aqh[2][4], aql[2][4], bkh[4][4], bkl[4][4];
                #pragma unroll
                for (int mt = 0; mt < 2; mt++) {
                    uint32_t row = warpM + mt * 16 + laA_r;
                    ldsm4(aqh[mt], sQh + swz(row, kb * 2 + laA_h));
                    ldsm4(aql[mt], sQl + swz(row, kb * 2 + laA_h));
                }
                #pragma unroll
                for (int np = 0; np < 4; np++) {
                    uint32_t row = c0 + np * 16 + laB_r;
                    ldsm4(bkh[np], sKh + swz(row, kb * 2 + laB_h));
                    ldsm4(bkl[np], sKl + swz(row, kb * 2 + laB_h));
                }
                #pragma unroll
                for (int mt = 0; mt < 2; mt++)
                    #pragma unroll
                    for (int n8 = 0; n8 < 8; n8++) {
                        const uint32_t* bh2 = &bkh[n8 >> 1][(n8 & 1) * 2];
                        const uint32_t* bl2 = &bkl[n8 >> 1][(n8 & 1) * 2];
                        mma_bf(S[mt][n8], aqh[mt], bh2);
                        mma_bf(S[mt][n8], aqh[mt], bl2);
                        mma_bf(S[mt][n8], aql[mt], bh2);
                    }
            }

            #pragma unroll
            for (int mt = 0; mt < 2; mt++) {
                #pragma unroll
                for (int half = 0; half < 2; half++) {
                    float cm = -1e30f;
                    #pragma unroll
                    for (int n8 = 0; n8 < 8; n8++) {
                        cm = fmaxf(cm, S[mt][n8][half * 2 + 0]);
                        cm = fmaxf(cm, S[mt][n8][half * 2 + 1]);
                    }
                    cm = fmaxf(cm, __shfl_xor_sync(0xffffffffu, cm, 1));
                    cm = fmaxf(cm, __shfl_xor_sync(0xffffffffu, cm, 2));
                    float mn = fmaxf(mS[mt][half], cm);
                    float corr = __expf(mS[mt][half] - mn);
                    float rs = 0.f;
                    #pragma unroll
                    for (int n8 = 0; n8 < 8; n8++) {
                        float p0 = __expf(S[mt][n8][half * 2 + 0] - mn);
                        float p1 = __expf(S[mt][n8][half * 2 + 1] - mn);
                        S[mt][n8][half * 2 + 0] = p0;
                        S[mt][n8][half * 2 + 1] = p1;
                        rs += p0 + p1;
                    }
                    rs += __shfl_xor_sync(0xffffffffu, rs, 1);
                    rs += __shfl_xor_sync(0xffffffffu, rs, 2);
                    lS[mt][half] = lS[mt][half] * corr + rs;
                    mS[mt][half] = mn;
                    #pragma unroll
                    for (int n8 = 0; n8 < 8; n8++) {
                        O[mt][n8][half * 2 + 0] *= corr;
                        O[mt][n8][half * 2 + 1] *= corr;
                    }
                }
            }

            #pragma unroll
            for (int kb = 0; kb < 4; kb++) {
                uint32_t ph[2][4], pl[2][4];
                #pragma unroll
                for (int mt = 0; mt < 2; mt++) {
                    #pragma unroll
                    for (int i = 0; i < 4; i++) {
                        int j = 2 * kb + (i >> 1);
                        float p0 = S[mt][j][(i & 1) * 2 + 0];
                        float p1 = S[mt][j][(i & 1) * 2 + 1];
                        __nv_bfloat16 h0 = __float2bfloat16(p0);
                        __nv_bfloat16 h1 = __float2bfloat16(p1);
                        ph[mt][i] = pack_bf2(h0, h1);
                        pl[mt][i] = pack_bf2(
                            __float2bfloat16(p0 - __bfloat162float(h0)),
                            __float2bfloat16(p1 - __bfloat162float(h1)));
                    }
                }
                uint32_t vfh[4][4], vfl[4][4];
                #pragma unroll
                for (int np = 0; np < 4; np++) {
                    uint32_t row = c0 + kb * 16 + (lane & 15);
                    uint32_t ch = np * 2 + (lane >> 4);
                    ldsm4t(vfh[np], sVh + swz(row, ch));
                    ldsm4t(vfl[np], sVl + swz(row, ch));
                }
                #pragma unroll
                for (int mt = 0; mt < 2; mt++)
                    #pragma unroll
                    for (int n8 = 0; n8 < 8; n8++) {
                        const uint32_t* vh2 = &vfh[n8 >> 1][(n8 & 1) * 2];
                        const uint32_t* vl2 = &vfl[n8 >> 1][(n8 & 1) * 2];
                        mma_bf(O[mt][n8], ph[mt], vh2);
                        mma_bf(O[mt][n8], ph[mt], vl2);
                        mma_bf(O[mt][n8], pl[mt], vh2);
                    }
            }
        }
    }

    #pragma unroll
    for (int mt = 0; mt < 2; mt++) {
        #pragma unroll
        for (int half = 0; half < 2; half++) {
            float inv = 1.f / lS[mt][half];
            int row = warpM + mt * 16 + (lane >> 2) + half * 8;
            size_t base = (size_t)(b * SEQ + w * WIN + row) * DIM + h * HD;
            #pragma unroll
            for (int n8 = 0; n8 < 8; n8++) {
                int col = n8 * 8 + (lane & 3) * 2;
                float x0 = O[mt][n8][half * 2 + 0] * inv;
                float x1 = O[mt][n8][half * 2 + 1] * inv;
                *(uint32_t*)(of + base + col) = pack_h2(x0, x1);
            }
        }
    }
}

// ---------------- host orchestration ---------------------------------------
extern "C" void kernel_launch(void* const* d_in, const int* in_sizes, int n_in,
                              void* d_out, int out_size) {
    const float* x      = (const float*)d_in[0];
    const float* t_emb  = (const float*)d_in[1];
    const float* ln1_g  = (const float*)d_in[2];
    const float* ln1_b  = (const float*)d_in[3];
    const float* qkv_w  = (const float*)d_in[4];
    const float* qkv_b  = (const float*)d_in[5];
    const float* proj_w = (const float*)d_in[6];
    const float* proj_b = (const float*)d_in[7];
    const float* ln2_g  = (const float*)d_in[8];
    const float* ln2_b  = (const float*)d_in[9];
    const float* mlp_w1 = (const float*)d_in[10];
    const float* mlp_b1 = (const float*)d_in[11];
    const float* mlp_w2 = (const float*)d_in[12];
    const float* mlp_b2 = (const float*)d_in[13];
    const float* time_w = (const float*)d_in[14];
    const float* time_b = (const float*)d_in[15];
    float* out = (float*)d_out;

    void* p;
    float *qkv, *y;
    __half *xf, *af, *ff;
    __half *wq, *wp, *w1, *w2;
    cudaGetSymbolAddress(&p, g_qkv);  qkv = (float*)p;
    cudaGetSymbolAddress(&p, g_y);    y   = (float*)p;
    cudaGetSymbolAddress(&p, g_xf);   xf  = (__half*)p;
    cudaGetSymbolAddress(&p, g_af);   af  = (__half*)p;
    cudaGetSymbolAddress(&p, g_ff);   ff  = (__half*)p;
    cudaGetSymbolAddress(&p, g_wq);   wq  = (__half*)p;
    cudaGetSymbolAddress(&p, g_wp);   wp  = (__half*)p;
    cudaGetSymbolAddress(&p, g_w1);   w1  = (__half*)p;
    cudaGetSymbolAddress(&p, g_w2);   w2  = (__half*)p;

    const int gemm_smem = 3 * STG;   // 96 KB (3-stage)
    cudaFuncSetAttribute(mma_gemm<0>, cudaFuncAttributeMaxDynamicSharedMemorySize, gemm_smem);
    cudaFuncSetAttribute(mma_gemm<1>, cudaFuncAttributeMaxDynamicSharedMemorySize, gemm_smem);
    cudaFuncSetAttribute(mma_gemm<2>, cudaFuncAttributeMaxDynamicSharedMemorySize, gemm_smem);
    const int attn_smem = 98304;
    cudaFuncSetAttribute(attn_mma_kernel, cudaFuncAttributeMaxDynamicSharedMemorySize, attn_smem);

    // 0. weight prep (transpose -> fp16)
    wprep_kernel<<<dim3(1536 / 32, 512 / 32), dim3(32, 8)>>>(qkv_w,  wq, 512, 1536);
    wprep_kernel<<<dim3(512 / 32,  512 / 32), dim3(32, 8)>>>(proj_w, wp, 512, 512);
    wprep_kernel<<<dim3(2048 / 32, 512 / 32), dim3(32, 8)>>>(mlp_w1, w1, 512, 2048);
    wprep_kernel<<<dim3(512 / 32, 2048 / 32), dim3(32, 8)>>>(mlp_w2, w2, 2048, 512);
    // 1. adaLN scale/shift
    time_mlp_kernel<<<dim3(2 * DIM / 256, B_), 256>>>(t_emb, time_w, time_b);
    // 2. modulated LN1 -> fp16
    ln_kernel<1><<<NTOK, 128>>>(x, ln1_g, ln1_b, xf);
    // 3. QKV GEMM -> fp32 qkv
    mma_gemm<0><<<dim3(12, NTOK / 128), 256, gemm_smem>>>(
        xf, wq, qkv_b, nullptr, qkv, nullptr, 512, 1536);
    // 4. local attention -> fp16
    attn_mma_kernel<<<dim3(NW, HEADS, B_), 128, attn_smem>>>(qkv, af);
    // 5. proj + residual(x) -> fp32 y
    mma_gemm<1><<<dim3(4, NTOK / 128), 256, gemm_smem>>>(
        af, wp, proj_b, x, y, nullptr, 512, 512);
    // 6. LN2 -> fp16
    ln_kernel<0><<<NTOK, 128>>>(y, ln2_g, ln2_b, xf);
    // 7. MLP up + GELU -> fp16
    mma_gemm<2><<<dim3(16, NTOK / 128), 256, gemm_smem>>>(
        xf, w1, mlp_b1, nullptr, nullptr, ff, 512, 2048);
    // 8. MLP down + residual(y) -> out
    mma_gemm<1><<<dim3(4, NTOK / 128), 256, gemm_smem>>>(
        ff, w2, mlp_b2, y, out, nullptr, 2048, 512);
}

// round 16
// speedup vs baseline: 1.7273x; 1.1339x over previous
#include <cuda_runtime.h>
#include <cuda_fp16.h>
#include <math.h>
#include <cstdint>

#define B_    8
#define SEQ   8192
#define DIM   512
#define HEADS 8
#define HD    64
#define FF_   2048
#define WIN   128
#define TD    512
#define NTOK  (B_*SEQ)
#define NW    (SEQ/WIN)

// ---------------- scratch (device globals; no runtime allocation) ----------
__device__ float g_ss  [B_ * 2 * DIM];
__device__ float g_y   [(size_t)NTOK * DIM];
__device__ __half g_xf [(size_t)NTOK * DIM];
__device__ __half g_af [(size_t)NTOK * DIM];
__device__ __half g_ff [(size_t)NTOK * FF_];
__device__ __half g_q  [(size_t)NTOK * DIM];   // pre-scaled by 0.125
__device__ __half g_kh [(size_t)NTOK * DIM];
__device__ __half g_kl [(size_t)NTOK * DIM];
__device__ __half g_v  [(size_t)NTOK * DIM];
__device__ __half g_wq[1536 * 512];
__device__ __half g_wp[512 * 512];
__device__ __half g_w1[2048 * 512];
__device__ __half g_w2[512 * 2048];

// ---------------- PTX helpers ----------------------------------------------
__device__ __forceinline__ uint32_t smem_u32(const void* p) {
    uint32_t a;
    asm("{ .reg .u64 t; cvta.to.shared.u64 t, %1; cvt.u32.u64 %0, t; }"
        : "=r"(a) : "l"(p));
    return a;
}
__device__ __forceinline__ void cp16(uint32_t dst, const void* src) {
    asm volatile("cp.async.cg.shared.global [%0], [%1], 16;"
                 :: "r"(dst), "l"(src) : "memory");
}
#define CP_COMMIT() asm volatile("cp.async.commit_group;" ::: "memory")
#define CP_WAIT(n)  asm volatile("cp.async.wait_group %0;" :: "n"(n) : "memory")

__device__ __forceinline__ void ldsm4(uint32_t* r, uint32_t addr) {
    asm volatile("ldmatrix.sync.aligned.m8n8.x4.shared.b16 {%0,%1,%2,%3}, [%4];"
                 : "=r"(r[0]), "=r"(r[1]), "=r"(r[2]), "=r"(r[3]) : "r"(addr));
}
__device__ __forceinline__ void ldsm4t(uint32_t* r, uint32_t addr) {
    asm volatile("ldmatrix.sync.aligned.m8n8.x4.trans.shared.b16 {%0,%1,%2,%3}, [%4];"
                 : "=r"(r[0]), "=r"(r[1]), "=r"(r[2]), "=r"(r[3]) : "r"(addr));
}
__device__ __forceinline__ void mma_fp(float* d, const uint32_t* a,
                                       const uint32_t* b) {
    asm volatile(
        "mma.sync.aligned.m16n8k16.row.col.f32.f16.f16.f32 "
        "{%0,%1,%2,%3}, {%4,%5,%6,%7}, {%8,%9}, {%0,%1,%2,%3};"
        : "+f"(d[0]), "+f"(d[1]), "+f"(d[2]), "+f"(d[3])
        : "r"(a[0]), "r"(a[1]), "r"(a[2]), "r"(a[3]), "r"(b[0]), "r"(b[1]));
}
__device__ __forceinline__ uint32_t swz(uint32_t r, uint32_t c16) {
    return (r << 7) + ((c16 ^ (r & 7)) << 4);
}
__device__ __forceinline__ uint32_t pack_h2(float a, float b) {
    __half2 p = __floats2half2_rn(a, b);
    return *reinterpret_cast<uint32_t*>(&p);
}

// ---------------- kernel 0: weight transpose -> single fp16 ----------------
__global__ void wprep_kernel(const float* __restrict__ W,
                             __half* __restrict__ oh, int K, int N) {
    __shared__ float tile[32][33];
    int bx = blockIdx.x * 32, by = blockIdx.y * 32;
    int tx = threadIdx.x, ty = threadIdx.y;
    #pragma unroll
    for (int i = 0; i < 4; i++) {
        int k = by + ty + i * 8;
        tile[ty + i * 8][tx] = W[(size_t)k * N + bx + tx];
    }
    __syncthreads();
    #pragma unroll
    for (int i = 0; i < 4; i++) {
        int n = bx + ty + i * 8;
        int k = by + tx;
        oh[(size_t)n * K + k] = __float2half_rn(tile[tx][ty + i * 8]);
    }
}

// ---------------- kernel 1: ss = silu(t_emb) @ time_w + time_b -------------
__global__ void time_mlp_kernel(const float* __restrict__ te,
                                const float* __restrict__ tw,
                                const float* __restrict__ tb) {
    __shared__ float st[TD];
    int b = blockIdx.y;
    for (int k = threadIdx.x; k < TD; k += blockDim.x) {
        float v = te[b * TD + k];
        st[k] = v / (1.f + __expf(-v));
    }
    __syncthreads();
    int j = blockIdx.x * blockDim.x + threadIdx.x;
    float acc = tb[j];
    for (int k = 0; k < TD; k++)
        acc = fmaf(st[k], tw[k * (2 * DIM) + j], acc);
    g_ss[b * 2 * DIM + j] = acc;
}

// ---------------- kernel 2: LayerNorm -> single fp16 -----------------------
template <int MOD>
__global__ void ln_kernel(const float* __restrict__ x,
                          const float* __restrict__ gam,
                          const float* __restrict__ bet,
                          __half* __restrict__ of) {
    int row  = blockIdx.x;
    int t    = threadIdx.x;
    int lane = t & 31, wid = t >> 5;
    float4 xv = ((const float4*)(x + (size_t)row * DIM))[t];
    float s  = xv.x + xv.y + xv.z + xv.w;
    float s2 = fmaf(xv.x, xv.x, fmaf(xv.y, xv.y, fmaf(xv.z, xv.z, xv.w * xv.w)));
    #pragma unroll
    for (int o = 16; o > 0; o >>= 1) {
        s  += __shfl_xor_sync(0xffffffffu, s,  o);
        s2 += __shfl_xor_sync(0xffffffffu, s2, o);
    }
    __shared__ float red[8];
    if (lane == 0) { red[wid] = s; red[4 + wid] = s2; }
    __syncthreads();
    s  = red[0] + red[1] + red[2] + red[3];
    s2 = red[4] + red[5] + red[6] + red[7];
    float mu   = s * (1.f / DIM);
    float var  = s2 * (1.f / DIM) - mu * mu;
    float rstd = rsqrtf(var + 1e-5f);

    float4 gg = ((const float4*)gam)[t];
    float4 bb = ((const float4*)bet)[t];
    float o4[4];
    o4[0] = (xv.x - mu) * rstd * gg.x + bb.x;
    o4[1] = (xv.y - mu) * rstd * gg.y + bb.y;
    o4[2] = (xv.z - mu) * rstd * gg.z + bb.z;
    o4[3] = (xv.w - mu) * rstd * gg.w + bb.w;
    if (MOD) {
        int b = row >> 13;
        float4 sc = ((const float4*)(g_ss + b * 2 * DIM))[t];
        float4 sh = ((const float4*)(g_ss + b * 2 * DIM + DIM))[t];
        o4[0] = o4[0] * (1.f + sc.x) + sh.x;
        o4[1] = o4[1] * (1.f + sc.y) + sh.y;
        o4[2] = o4[2] * (1.f + sc.z) + sh.z;
        o4[3] = o4[3] * (1.f + sc.w) + sh.w;
    }
    ((uint2*)(of + (size_t)row * DIM))[t] =
        make_uint2(pack_h2(o4[0], o4[1]), pack_h2(o4[2], o4[3]));
}

// ---------------- kernel 3: single-fp16 GEMM, 3-stage pipeline -------------
// EPI: 0 = bias -> f32; 1 = bias+res -> f32; 2 = bias+GELU -> fp16;
//      3 = QKV epilogue -> q fp16 (x0.125) | k fp16 hi/lo | v fp16
#define KSTEP 64
#define STG   32768
template <int EPI>
__global__ __launch_bounds__(256, 2)
void mma_gemm(const __half* __restrict__ A,
              const __half* __restrict__ B,
              const float* __restrict__ bias,
              const float* __restrict__ res,
              float* __restrict__ Cf,
              __half* __restrict__ Ch,
              __half* __restrict__ Ckh,
              __half* __restrict__ Ckl,
              __half* __restrict__ Cv,
              int K, int N) {
    extern __shared__ char smem[];
    const uint32_t sbase = smem_u32(smem);
    const int tid = threadIdx.x, w = tid >> 5, lane = tid & 31;
    const int bm = blockIdx.y * 128, bn = blockIdx.x * 128;
    const int warpM = (w >> 2) * 64, warpN = (w & 3) * 32;
    const int T = K / KSTEP;

    const int r_ld = tid >> 3, c_ld = tid & 7;

    auto issue = [&](int t) {
        int k0 = t * KSTEP;
        uint32_t sa = sbase + (t % 3) * STG;
        uint32_t sb = sa + 16384;
        #pragma unroll
        for (int i = 0; i < 4; i++) {
            int r = r_ld + i * 32;
            uint32_t off = swz((uint32_t)r, (uint32_t)c_ld);
            cp16(sa + off, A + (size_t)(bm + r) * K + k0 + c_ld * 8);
            cp16(sb + off, B + (size_t)(bn + r) * K + k0 + c_ld * 8);
        }
        CP_COMMIT();
    };

    float acc[4][4][4];
    #pragma unroll
    for (int i = 0; i < 4; i++)
        #pragma unroll
        for (int j = 0; j < 4; j++)
            #pragma unroll
            for (int e = 0; e < 4; e++) acc[i][j][e] = 0.f;

    const int laA_r = lane & 15, laA_h = lane >> 4;
    const int laB_r = (lane & 7) + ((lane >> 4) << 3);
    const int laB_h = (lane >> 3) & 1;

    issue(0);
    issue(1);
    for (int t = 0; t < T; t++) {
        if (t < T - 1) { CP_WAIT(1); } else { CP_WAIT(0); }
        __syncthreads();
        if (t + 2 < T) issue(t + 2);

        uint32_t sa = sbase + (t % 3) * STG;
        uint32_t sb = sa + 16384;
        #pragma unroll
        for (int i = 0; i < 4; i++) {
            uint32_t af[4][4], bf[2][4];
            #pragma unroll
            for (int mi = 0; mi < 4; mi++) {
                uint32_t row = warpM + mi * 16 + laA_r;
                ldsm4(af[mi], sa + swz(row, 2 * i + laA_h));
            }
            #pragma unroll
            for (int nj = 0; nj < 2; nj++) {
                uint32_t row = warpN + nj * 16 + laB_r;
                ldsm4(bf[nj], sb + swz(row, 2 * i + laB_h));
            }
            #pragma unroll
            for (int mi = 0; mi < 4; mi++)
                #pragma unroll
                for (int n8 = 0; n8 < 4; n8++)
                    mma_fp(acc[mi][n8], af[mi], &bf[n8 >> 1][(n8 & 1) * 2]);
        }
    }

    int tr = lane >> 2, tc = (lane & 3) * 2;
    #pragma unroll
    for (int mi = 0; mi < 4; mi++) {
        #pragma unroll
        for (int half = 0; half < 2; half++) {
            int row = bm + warpM + mi * 16 + tr + half * 8;
            size_t rowoff = (size_t)row * N;
            #pragma unroll
            for (int n8 = 0; n8 < 4; n8++) {
                int col = bn + warpN + n8 * 8 + tc;
                float2 bi = *(const float2*)(bias + col);
                float ox = acc[mi][n8][half * 2 + 0] + bi.x;
                float oy = acc[mi][n8][half * 2 + 1] + bi.y;
                if (EPI == 1) {
                    float2 rr = *(const float2*)(res + rowoff + col);
                    ox += rr.x; oy += rr.y;
                }
                if (EPI == 2) {
                    ox = 0.5f * ox * (1.f + erff(ox * 0.70710678118654752f));
                    oy = 0.5f * oy * (1.f + erff(oy * 0.70710678118654752f));
                    *(uint32_t*)(Ch + rowoff + col) = pack_h2(ox, oy);
                } else if (EPI == 3) {
                    size_t ro = (size_t)row * DIM;
                    if (col < 512) {
                        *(uint32_t*)(Ch + ro + col) =
                            pack_h2(ox * 0.125f, oy * 0.125f);
                    } else if (col < 1024) {
                        int c = col - 512;
                        __half hx = __float2half_rn(ox);
                        __half hy = __float2half_rn(oy);
                        __half2 hp = __halves2half2(hx, hy);
                        *(uint32_t*)(Ckh + ro + c) = *(uint32_t*)&hp;
                        *(uint32_t*)(Ckl + ro + c) =
                            pack_h2(ox - __half2float(hx), oy - __half2float(hy));
                    } else {
                        int c = col - 1024;
                        *(uint32_t*)(Cv + ro + c) = pack_h2(ox, oy);
                    }
                } else {
                    *(float2*)(Cf + rowoff + col) = make_float2(ox, oy);
                }
            }
        }
    }
}

// ---------------- kernel 4: local windowed attention (fp16-native) ---------
__global__ __launch_bounds__(128)
void attn_mma_kernel(const __half* __restrict__ q,
                     const __half* __restrict__ kh,
                     const __half* __restrict__ kl,
                     const __half* __restrict__ v,
                     __half* __restrict__ of) {
    extern __shared__ char smc[];
    const uint32_t sQ  = smem_u32(smc);
    const uint32_t sKh = sQ + 16384;
    const uint32_t sKl = sQ + 32768;
    const uint32_t sV  = sQ + 49152;

    const int w = blockIdx.x, h = blockIdx.y, b = blockIdx.z;
    const int tid = threadIdx.x, lane = tid & 31;
    const int warpM = (tid >> 5) * 32;

    const int laA_r = lane & 15, laA_h = lane >> 4;
    const int laB_r = (lane & 7) + ((lane >> 4) << 3);
    const int laB_h = (lane >> 3) & 1;

    {
        size_t base = (size_t)(b * SEQ + w * WIN + tid) * DIM + h * HD;
        const uint4* qp = (const uint4*)(q + base);
        #pragma unroll
        for (int c = 0; c < 8; c++)
            *(uint4*)(smc + swz((uint32_t)tid, (uint32_t)c)) = qp[c];
    }

    float O[2][8][4];
    #pragma unroll
    for (int mt = 0; mt < 2; mt++)
        #pragma unroll
        for (int n8 = 0; n8 < 8; n8++)
            #pragma unroll
            for (int e = 0; e < 4; e++) O[mt][n8][e] = 0.f;
    float mS[2][2] = {{-1e30f, -1e30f}, {-1e30f, -1e30f}};
    float lS[2][2] = {{0.f, 0.f}, {0.f, 0.f}};

    for (int dw = -1; dw <= 1; dw++) {
        int wi = w + dw;
        if (wi < 0 || wi >= NW) continue;
        __syncthreads();
        {
            size_t base = (size_t)(b * SEQ + wi * WIN + tid) * DIM + h * HD;
            const uint4* khp = (const uint4*)(kh + base);
            const uint4* klp = (const uint4*)(kl + base);
            const uint4* vp  = (const uint4*)(v + base);
            #pragma unroll
            for (int c = 0; c < 8; c++) {
                uint32_t off = swz((uint32_t)tid, (uint32_t)c);
                *(uint4*)(smc + 16384 + off) = khp[c];
                *(uint4*)(smc + 32768 + off) = klp[c];
                *(uint4*)(smc + 49152 + off) = vp[c];
            }
        }
        __syncthreads();

        #pragma unroll
        for (int c0 = 0; c0 < 128; c0 += 64) {
            float S[2][8][4];
            #pragma unroll
            for (int mt = 0; mt < 2; mt++)
                #pragma unroll
                for (int n8 = 0; n8 < 8; n8++)
                    #pragma unroll
                    for (int e = 0; e < 4; e++) S[mt][n8][e] = 0.f;

            #pragma unroll
            for (int kb = 0; kb < 4; kb++) {
                uint32_t aq[2][4], bh[4][4], bl[4][4];
                #pragma unroll
                for (int mt = 0; mt < 2; mt++) {
                    uint32_t row = warpM + mt * 16 + laA_r;
                    ldsm4(aq[mt], sQ + swz(row, kb * 2 + laA_h));
                }
                #pragma unroll
                for (int np = 0; np < 4; np++) {
                    uint32_t row = c0 + np * 16 + laB_r;
                    ldsm4(bh[np], sKh + swz(row, kb * 2 + laB_h));
                    ldsm4(bl[np], sKl + swz(row, kb * 2 + laB_h));
                }
                #pragma unroll
                for (int mt = 0; mt < 2; mt++)
                    #pragma unroll
                    for (int n8 = 0; n8 < 8; n8++) {
                        mma_fp(S[mt][n8], aq[mt], &bh[n8 >> 1][(n8 & 1) * 2]);
                        mma_fp(S[mt][n8], aq[mt], &bl[n8 >> 1][(n8 & 1) * 2]);
                    }
            }

            #pragma unroll
            for (int mt = 0; mt < 2; mt++) {
                #pragma unroll
                for (int half = 0; half < 2; half++) {
                    float cm = -1e30f;
                    #pragma unroll
                    for (int n8 = 0; n8 < 8; n8++) {
                        cm = fmaxf(cm, S[mt][n8][half * 2 + 0]);
                        cm = fmaxf(cm, S[mt][n8][half * 2 + 1]);
                    }
                    cm = fmaxf(cm, __shfl_xor_sync(0xffffffffu, cm, 1));
                    cm = fmaxf(cm, __shfl_xor_sync(0xffffffffu, cm, 2));
                    float mn = fmaxf(mS[mt][half], cm);
                    float corr = __expf(mS[mt][half] - mn);
                    float rs = 0.f;
                    #pragma unroll
                    for (int n8 = 0; n8 < 8; n8++) {
                        float p0 = __expf(S[mt][n8][half * 2 + 0] - mn);
                        float p1 = __expf(S[mt][n8][half * 2 + 1] - mn);
                        S[mt][n8][half * 2 + 0] = p0;
                        S[mt][n8][half * 2 + 1] = p1;
                        rs += p0 + p1;
                    }
                    rs += __shfl_xor_sync(0xffffffffu, rs, 1);
                    rs += __shfl_xor_sync(0xffffffffu, rs, 2);
                    lS[mt][half] = lS[mt][half] * corr + rs;
                    mS[mt][half] = mn;
                    #pragma unroll
                    for (int n8 = 0; n8 < 8; n8++) {
                        O[mt][n8][half * 2 + 0] *= corr;
                        O[mt][n8][half * 2 + 1] *= corr;
                    }
                }
            }

            #pragma unroll
            for (int kb = 0; kb < 4; kb++) {
                uint32_t ph[2][4];
                #pragma unroll
                for (int mt = 0; mt < 2; mt++) {
                    #pragma unroll
                    for (int i = 0; i < 4; i++) {
                        int j = 2 * kb + (i >> 1);
                        ph[mt][i] = pack_h2(S[mt][j][(i & 1) * 2 + 0],
                                            S[mt][j][(i & 1) * 2 + 1]);
                    }
                }
                uint32_t vf[4][4];
                #pragma unroll
                for (int np = 0; np < 4; np++) {
                    uint32_t row = c0 + kb * 16 + (lane & 15);
                    uint32_t ch = np * 2 + (lane >> 4);
                    ldsm4t(vf[np], sV + swz(row, ch));
                }
                #pragma unroll
                for (int mt = 0; mt < 2; mt++)
                    #pragma unroll
                    for (int n8 = 0; n8 < 8; n8++)
                        mma_fp(O[mt][n8], ph[mt], &vf[n8 >> 1][(n8 & 1) * 2]);
            }
        }
    }

    #pragma unroll
    for (int mt = 0; mt < 2; mt++) {
        #pragma unroll
        for (int half = 0; half < 2; half++) {
            float inv = 1.f / lS[mt][half];
            int row = warpM + mt * 16 + (lane >> 2) + half * 8;
            size_t base = (size_t)(b * SEQ + w * WIN + row) * DIM + h * HD;
            #pragma unroll
            for (int n8 = 0; n8 < 8; n8++) {
                int col = n8 * 8 + (lane & 3) * 2;
                *(uint32_t*)(of + base + col) =
                    pack_h2(O[mt][n8][half * 2 + 0] * inv,
                            O[mt][n8][half * 2 + 1] * inv);
            }
        }
    }
}

// ---------------- host orchestration ---------------------------------------
extern "C" void kernel_launch(void* const* d_in, const int* in_sizes, int n_in,
                              void* d_out, int out_size) {
    const float* x      = (const float*)d_in[0];
    const float* t_emb  = (const float*)d_in[1];
    const float* ln1_g  = (const float*)d_in[2];
    const float* ln1_b  = (const float*)d_in[3];
    const float* qkv_w  = (const float*)d_in[4];
    const float* qkv_b  = (const float*)d_in[5];
    const float* proj_w = (const float*)d_in[6];
    const float* proj_b = (const float*)d_in[7];
    const float* ln2_g  = (const float*)d_in[8];
    const float* ln2_b  = (const float*)d_in[9];
    const float* mlp_w1 = (const float*)d_in[10];
    const float* mlp_b1 = (const float*)d_in[11];
    const float* mlp_w2 = (const float*)d_in[12];
    const float* mlp_b2 = (const float*)d_in[13];
    const float* time_w = (const float*)d_in[14];
    const float* time_b = (const float*)d_in[15];
    float* out = (float*)d_out;

    void* p;
    float* y;
    __half *xf, *af, *ff, *q, *kh, *kl, *v;
    __half *wq, *wp, *w1, *w2;
    cudaGetSymbolAddress(&p, g_y);    y   = (float*)p;
    cudaGetSymbolAddress(&p, g_xf);   xf  = (__half*)p;
    cudaGetSymbolAddress(&p, g_af);   af  = (__half*)p;
    cudaGetSymbolAddress(&p, g_ff);   ff  = (__half*)p;
    cudaGetSymbolAddress(&p, g_q);    q   = (__half*)p;
    cudaGetSymbolAddress(&p, g_kh);   kh  = (__half*)p;
    cudaGetSymbolAddress(&p, g_kl);   kl  = (__half*)p;
    cudaGetSymbolAddress(&p, g_v);    v   = (__half*)p;
    cudaGetSymbolAddress(&p, g_wq);   wq  = (__half*)p;
    cudaGetSymbolAddress(&p, g_wp);   wp  = (__half*)p;
    cudaGetSymbolAddress(&p, g_w1);   w1  = (__half*)p;
    cudaGetSymbolAddress(&p, g_w2);   w2  = (__half*)p;

    const int gemm_smem = 3 * STG;
    cudaFuncSetAttribute(mma_gemm<0>, cudaFuncAttributeMaxDynamicSharedMemorySize, gemm_smem);
    cudaFuncSetAttribute(mma_gemm<1>, cudaFuncAttributeMaxDynamicSharedMemorySize, gemm_smem);
    cudaFuncSetAttribute(mma_gemm<2>, cudaFuncAttributeMaxDynamicSharedMemorySize, gemm_smem);
    cudaFuncSetAttribute(mma_gemm<3>, cudaFuncAttributeMaxDynamicSharedMemorySize, gemm_smem);
    const int attn_smem = 65536;
    cudaFuncSetAttribute(attn_mma_kernel, cudaFuncAttributeMaxDynamicSharedMemorySize, attn_smem);

    wprep_kernel<<<dim3(1536 / 32, 512 / 32), dim3(32, 8)>>>(qkv_w,  wq, 512, 1536);
    wprep_kernel<<<dim3(512 / 32,  512 / 32), dim3(32, 8)>>>(proj_w, wp, 512, 512);
    wprep_kernel<<<dim3(2048 / 32, 512 / 32), dim3(32, 8)>>>(mlp_w1, w1, 512, 2048);
    wprep_kernel<<<dim3(512 / 32, 2048 / 32), dim3(32, 8)>>>(mlp_w2, w2, 2048, 512);
    time_mlp_kernel<<<dim3(2 * DIM / 256, B_), 256>>>(t_emb, time_w, time_b);
    ln_kernel<1><<<NTOK, 128>>>(x, ln1_g, ln1_b, xf);
    mma_gemm<3><<<dim3(12, NTOK / 128), 256, gemm_smem>>>(
        xf, wq, qkv_b, nullptr, nullptr, q, kh, kl, v, 512, 1536);
    attn_mma_kernel<<<dim3(NW, HEADS, B_), 128, attn_smem>>>(q, kh, kl, v, af);
    mma_gemm<1><<<dim3(4, NTOK / 128), 256, gemm_smem>>>(
        af, wp, proj_b, x, y, nullptr, nullptr, nullptr, nullptr, 512, 512);
    ln_kernel<0><<<NTOK, 128>>>(y, ln2_g, ln2_b, xf);
    mma_gemm<2><<<dim3(16, NTOK / 128), 256, gemm_smem>>>(
        xf, w1, mlp_b1, nullptr, nullptr, ff, nullptr, nullptr, nullptr, 512, 2048);
    mma_gemm<1><<<dim3(4, NTOK / 128), 256, gemm_smem>>>(
        ff, w2, mlp_b2, y, out, nullptr, nullptr, nullptr, nullptr, 2048, 512);
}

// round 17
// speedup vs baseline: 1.7406x; 1.0077x over previous
#include <cuda_runtime.h>
#include <cuda_fp16.h>
#include <math.h>
#include <cstdint>

#define B_    8
#define SEQ   8192
#define DIM   512
#define HEADS 8
#define HD    64
#define FF_   2048
#define WIN   128
#define TD    512
#define NTOK  (B_*SEQ)
#define NW    (SEQ/WIN)

// ---------------- scratch (device globals; no runtime allocation) ----------
__device__ float g_ss  [B_ * 2 * DIM];
__device__ float g_y   [(size_t)NTOK * DIM];
__device__ __half g_xf [(size_t)NTOK * DIM];
__device__ __half g_af [(size_t)NTOK * DIM];
__device__ __half g_ff [(size_t)NTOK * FF_];
__device__ __half g_q  [(size_t)NTOK * DIM];   // pre-scaled by 0.125
__device__ __half g_kh [(size_t)NTOK * DIM];
__device__ __half g_kl [(size_t)NTOK * DIM];
__device__ __half g_v  [(size_t)NTOK * DIM];
__device__ __half g_wq[1536 * 512];
__device__ __half g_wp[512 * 512];
__device__ __half g_w1[2048 * 512];
__device__ __half g_w2[512 * 2048];

// ---------------- PTX helpers ----------------------------------------------
__device__ __forceinline__ uint32_t smem_u32(const void* p) {
    uint32_t a;
    asm("{ .reg .u64 t; cvta.to.shared.u64 t, %1; cvt.u32.u64 %0, t; }"
        : "=r"(a) : "l"(p));
    return a;
}
__device__ __forceinline__ void cp16(uint32_t dst, const void* src) {
    asm volatile("cp.async.cg.shared.global [%0], [%1], 16;"
                 :: "r"(dst), "l"(src) : "memory");
}
#define CP_COMMIT() asm volatile("cp.async.commit_group;" ::: "memory")
#define CP_WAIT(n)  asm volatile("cp.async.wait_group %0;" :: "n"(n) : "memory")

__device__ __forceinline__ void ldsm4(uint32_t* r, uint32_t addr) {
    asm volatile("ldmatrix.sync.aligned.m8n8.x4.shared.b16 {%0,%1,%2,%3}, [%4];"
                 : "=r"(r[0]), "=r"(r[1]), "=r"(r[2]), "=r"(r[3]) : "r"(addr));
}
__device__ __forceinline__ void ldsm4t(uint32_t* r, uint32_t addr) {
    asm volatile("ldmatrix.sync.aligned.m8n8.x4.trans.shared.b16 {%0,%1,%2,%3}, [%4];"
                 : "=r"(r[0]), "=r"(r[1]), "=r"(r[2]), "=r"(r[3]) : "r"(addr));
}
__device__ __forceinline__ void mma_fp(float* d, const uint32_t* a,
                                       const uint32_t* b) {
    asm volatile(
        "mma.sync.aligned.m16n8k16.row.col.f32.f16.f16.f32 "
        "{%0,%1,%2,%3}, {%4,%5,%6,%7}, {%8,%9}, {%0,%1,%2,%3};"
        : "+f"(d[0]), "+f"(d[1]), "+f"(d[2]), "+f"(d[3])
        : "r"(a[0]), "r"(a[1]), "r"(a[2]), "r"(a[3]), "r"(b[0]), "r"(b[1]));
}
__device__ __forceinline__ uint32_t swz(uint32_t r, uint32_t c16) {
    return (r << 7) + ((c16 ^ (r & 7)) << 4);
}
__device__ __forceinline__ uint32_t pack_h2(float a, float b) {
    __half2 p = __floats2half2_rn(a, b);
    return *reinterpret_cast<uint32_t*>(&p);
}

// ---------------- kernel 0: weight transpose -> single fp16 ----------------
__global__ void wprep_kernel(const float* __restrict__ W,
                             __half* __restrict__ oh, int K, int N) {
    __shared__ float tile[32][33];
    int bx = blockIdx.x * 32, by = blockIdx.y * 32;
    int tx = threadIdx.x, ty = threadIdx.y;
    #pragma unroll
    for (int i = 0; i < 4; i++) {
        int k = by + ty + i * 8;
        tile[ty + i * 8][tx] = W[(size_t)k * N + bx + tx];
    }
    __syncthreads();
    #pragma unroll
    for (int i = 0; i < 4; i++) {
        int n = bx + ty + i * 8;
        int k = by + tx;
        oh[(size_t)n * K + k] = __float2half_rn(tile[tx][ty + i * 8]);
    }
}

// ---------------- kernel 1: ss = silu(t_emb) @ time_w + time_b -------------
__global__ void time_mlp_kernel(const float* __restrict__ te,
                                const float* __restrict__ tw,
                                const float* __restrict__ tb) {
    __shared__ float st[TD];
    int b = blockIdx.y;
    for (int k = threadIdx.x; k < TD; k += blockDim.x) {
        float v = te[b * TD + k];
        st[k] = v / (1.f + __expf(-v));
    }
    __syncthreads();
    int j = blockIdx.x * blockDim.x + threadIdx.x;
    float acc = tb[j];
    for (int k = 0; k < TD; k++)
        acc = fmaf(st[k], tw[k * (2 * DIM) + j], acc);
    g_ss[b * 2 * DIM + j] = acc;
}

// ---------------- kernel 2: LayerNorm, warp-per-row -> fp16 ----------------
// 256 threads = 8 warps = 8 rows per block; pure shfl reduction, no smem.
template <int MOD>
__global__ __launch_bounds__(256)
void ln_kernel(const float* __restrict__ x,
               const float* __restrict__ gam,
               const float* __restrict__ bet,
               __half* __restrict__ of) {
    int row  = blockIdx.x * 8 + (threadIdx.x >> 5);
    int lane = threadIdx.x & 31;
    const float4* xp = (const float4*)(x + (size_t)row * DIM);

    float4 xv[4];
    float s = 0.f, s2 = 0.f;
    #pragma unroll
    for (int i = 0; i < 4; i++) {
        xv[i] = xp[lane + i * 32];
        s  += xv[i].x + xv[i].y + xv[i].z + xv[i].w;
        s2 += fmaf(xv[i].x, xv[i].x, fmaf(xv[i].y, xv[i].y,
                   fmaf(xv[i].z, xv[i].z, xv[i].w * xv[i].w)));
    }
    #pragma unroll
    for (int o = 16; o > 0; o >>= 1) {
        s  += __shfl_xor_sync(0xffffffffu, s,  o);
        s2 += __shfl_xor_sync(0xffffffffu, s2, o);
    }
    float mu   = s * (1.f / DIM);
    float var  = s2 * (1.f / DIM) - mu * mu;
    float rstd = rsqrtf(var + 1e-5f);

    int b = row >> 13;
    uint2* op = (uint2*)(of + (size_t)row * DIM);
    #pragma unroll
    for (int i = 0; i < 4; i++) {
        int c4 = lane + i * 32;
        float4 gg = ((const float4*)gam)[c4];
        float4 bb = ((const float4*)bet)[c4];
        float o0 = (xv[i].x - mu) * rstd * gg.x + bb.x;
        float o1 = (xv[i].y - mu) * rstd * gg.y + bb.y;
        float o2 = (xv[i].z - mu) * rstd * gg.z + bb.z;
        float o3 = (xv[i].w - mu) * rstd * gg.w + bb.w;
        if (MOD) {
            float4 sc = ((const float4*)(g_ss + b * 2 * DIM))[c4];
            float4 sh = ((const float4*)(g_ss + b * 2 * DIM + DIM))[c4];
            o0 = o0 * (1.f + sc.x) + sh.x;
            o1 = o1 * (1.f + sc.y) + sh.y;
            o2 = o2 * (1.f + sc.z) + sh.z;
            o3 = o3 * (1.f + sc.w) + sh.w;
        }
        op[c4] = make_uint2(pack_h2(o0, o1), pack_h2(o2, o3));
    }
}

// ---------------- kernel 3: single-fp16 GEMM, 3-stage pipeline -------------
// EPI: 0 = bias -> f32; 1 = bias+res -> f32; 2 = bias+GELU -> fp16;
//      3 = QKV epilogue -> q fp16 (x0.125) | k fp16 hi/lo | v fp16
#define KSTEP 64
#define STG   32768
template <int EPI>
__global__ __launch_bounds__(256, 2)
void mma_gemm(const __half* __restrict__ A,
              const __half* __restrict__ B,
              const float* __restrict__ bias,
              const float* __restrict__ res,
              float* __restrict__ Cf,
              __half* __restrict__ Ch,
              __half* __restrict__ Ckh,
              __half* __restrict__ Ckl,
              __half* __restrict__ Cv,
              int K, int N) {
    extern __shared__ char smem[];
    const uint32_t sbase = smem_u32(smem);
    const int tid = threadIdx.x, w = tid >> 5, lane = tid & 31;
    const int bm = blockIdx.y * 128, bn = blockIdx.x * 128;
    const int warpM = (w >> 2) * 64, warpN = (w & 3) * 32;
    const int T = K / KSTEP;

    const int r_ld = tid >> 3, c_ld = tid & 7;

    auto issue = [&](int t) {
        int k0 = t * KSTEP;
        uint32_t sa = sbase + (t % 3) * STG;
        uint32_t sb = sa + 16384;
        #pragma unroll
        for (int i = 0; i < 4; i++) {
            int r = r_ld + i * 32;
            uint32_t off = swz((uint32_t)r, (uint32_t)c_ld);
            cp16(sa + off, A + (size_t)(bm + r) * K + k0 + c_ld * 8);
            cp16(sb + off, B + (size_t)(bn + r) * K + k0 + c_ld * 8);
        }
        CP_COMMIT();
    };

    float acc[4][4][4];
    #pragma unroll
    for (int i = 0; i < 4; i++)
        #pragma unroll
        for (int j = 0; j < 4; j++)
            #pragma unroll
            for (int e = 0; e < 4; e++) acc[i][j][e] = 0.f;

    const int laA_r = lane & 15, laA_h = lane >> 4;
    const int laB_r = (lane & 7) + ((lane >> 4) << 3);
    const int laB_h = (lane >> 3) & 1;

    issue(0);
    issue(1);
    for (int t = 0; t < T; t++) {
        if (t < T - 1) { CP_WAIT(1); } else { CP_WAIT(0); }
        __syncthreads();
        if (t + 2 < T) issue(t + 2);

        uint32_t sa = sbase + (t % 3) * STG;
        uint32_t sb = sa + 16384;
        #pragma unroll
        for (int i = 0; i < 4; i++) {
            uint32_t af[4][4], bf[2][4];
            #pragma unroll
            for (int mi = 0; mi < 4; mi++) {
                uint32_t row = warpM + mi * 16 + laA_r;
                ldsm4(af[mi], sa + swz(row, 2 * i + laA_h));
            }
            #pragma unroll
            for (int nj = 0; nj < 2; nj++) {
                uint32_t row = warpN + nj * 16 + laB_r;
                ldsm4(bf[nj], sb + swz(row, 2 * i + laB_h));
            }
            #pragma unroll
            for (int mi = 0; mi < 4; mi++)
                #pragma unroll
                for (int n8 = 0; n8 < 4; n8++)
                    mma_fp(acc[mi][n8], af[mi], &bf[n8 >> 1][(n8 & 1) * 2]);
        }
    }

    int tr = lane >> 2, tc = (lane & 3) * 2;
    #pragma unroll
    for (int mi = 0; mi < 4; mi++) {
        #pragma unroll
        for (int half = 0; half < 2; half++) {
            int row = bm + warpM + mi * 16 + tr + half * 8;
            size_t rowoff = (size_t)row * N;
            #pragma unroll
            for (int n8 = 0; n8 < 4; n8++) {
                int col = bn + warpN + n8 * 8 + tc;
                float2 bi = *(const float2*)(bias + col);
                float ox = acc[mi][n8][half * 2 + 0] + bi.x;
                float oy = acc[mi][n8][half * 2 + 1] + bi.y;
                if (EPI == 1) {
                    float2 rr = *(const float2*)(res + rowoff + col);
                    ox += rr.x; oy += rr.y;
                }
                if (EPI == 2) {
                    ox = 0.5f * ox * (1.f + erff(ox * 0.70710678118654752f));
                    oy = 0.5f * oy * (1.f + erff(oy * 0.70710678118654752f));
                    *(uint32_t*)(Ch + rowoff + col) = pack_h2(ox, oy);
                } else if (EPI == 3) {
                    size_t ro = (size_t)row * DIM;
                    if (col < 512) {
                        *(uint32_t*)(Ch + ro + col) =
                            pack_h2(ox * 0.125f, oy * 0.125f);
                    } else if (col < 1024) {
                        int c = col - 512;
                        __half hx = __float2half_rn(ox);
                        __half hy = __float2half_rn(oy);
                        __half2 hp = __halves2half2(hx, hy);
                        *(uint32_t*)(Ckh + ro + c) = *(uint32_t*)&hp;
                        *(uint32_t*)(Ckl + ro + c) =
                            pack_h2(ox - __half2float(hx), oy - __half2float(hy));
                    } else {
                        int c = col - 1024;
                        *(uint32_t*)(Cv + ro + c) = pack_h2(ox, oy);
                    }
                } else {
                    *(float2*)(Cf + rowoff + col) = make_float2(ox, oy);
                }
            }
        }
    }
}

// ---------------- kernel 4: local windowed attention (fp16-native) ---------
__global__ __launch_bounds__(128)
void attn_mma_kernel(const __half* __restrict__ q,
                     const __half* __restrict__ kh,
                     const __half* __restrict__ kl,
                     const __half* __restrict__ v,
                     __half* __restrict__ of) {
    extern __shared__ char smc[];
    const uint32_t sQ  = smem_u32(smc);
    const uint32_t sKh = sQ + 16384;
    const uint32_t sKl = sQ + 32768;
    const uint32_t sV  = sQ + 49152;

    const int w = blockIdx.x, h = blockIdx.y, b = blockIdx.z;
    const int tid = threadIdx.x, lane = tid & 31;
    const int warpM = (tid >> 5) * 32;

    const int laA_r = lane & 15, laA_h = lane >> 4;
    const int laB_r = (lane & 7) + ((lane >> 4) << 3);
    const int laB_h = (lane >> 3) & 1;

    {
        size_t base = (size_t)(b * SEQ + w * WIN + tid) * DIM + h * HD;
        const uint4* qp = (const uint4*)(q + base);
        #pragma unroll
        for (int c = 0; c < 8; c++)
            *(uint4*)(smc + swz((uint32_t)tid, (uint32_t)c)) = qp[c];
    }

    float O[2][8][4];
    #pragma unroll
    for (int mt = 0; mt < 2; mt++)
        #pragma unroll
        for (int n8 = 0; n8 < 8; n8++)
            #pragma unroll
            for (int e = 0; e < 4; e++) O[mt][n8][e] = 0.f;
    float mS[2][2] = {{-1e30f, -1e30f}, {-1e30f, -1e30f}};
    float lS[2][2] = {{0.f, 0.f}, {0.f, 0.f}};

    for (int dw = -1; dw <= 1; dw++) {
        int wi = w + dw;
        if (wi < 0 || wi >= NW) continue;
        __syncthreads();
        {
            size_t base = (size_t)(b * SEQ + wi * WIN + tid) * DIM + h * HD;
            const uint4* khp = (const uint4*)(kh + base);
            const uint4* klp = (const uint4*)(kl + base);
            const uint4* vp  = (const uint4*)(v + base);
            #pragma unroll
            for (int c = 0; c < 8; c++) {
                uint32_t off = swz((uint32_t)tid, (uint32_t)c);
                *(uint4*)(smc + 16384 + off) = khp[c];
                *(uint4*)(smc + 32768 + off) = klp[c];
                *(uint4*)(smc + 49152 + off) = vp[c];
            }
        }
        __syncthreads();

        #pragma unroll
        for (int c0 = 0; c0 < 128; c0 += 64) {
            float S[2][8][4];
            #pragma unroll
            for (int mt = 0; mt < 2; mt++)
                #pragma unroll
                for (int n8 = 0; n8 < 8; n8++)
                    #pragma unroll
                    for (int e = 0; e < 4; e++) S[mt][n8][e] = 0.f;

            #pragma unroll
            for (int kb = 0; kb < 4; kb++) {
                uint32_t aq[2][4], bh[4][4], bl[4][4];
                #pragma unroll
                for (int mt = 0; mt < 2; mt++) {
                    uint32_t row = warpM + mt * 16 + laA_r;
                    ldsm4(aq[mt], sQ + swz(row, kb * 2 + laA_h));
                }
                #pragma unroll
                for (int np = 0; np < 4; np++) {
                    uint32_t row = c0 + np * 16 + laB_r;
                    ldsm4(bh[np], sKh + swz(row, kb * 2 + laB_h));
                    ldsm4(bl[np], sKl + swz(row, kb * 2 + laB_h));
                }
                #pragma unroll
                for (int mt = 0; mt < 2; mt++)
                    #pragma unroll
                    for (int n8 = 0; n8 < 8; n8++) {
                        mma_fp(S[mt][n8], aq[mt], &bh[n8 >> 1][(n8 & 1) * 2]);
                        mma_fp(S[mt][n8], aq[mt], &bl[n8 >> 1][(n8 & 1) * 2]);
                    }
            }

            #pragma unroll
            for (int mt = 0; mt < 2; mt++) {
                #pragma unroll
                for (int half = 0; half < 2; half++) {
                    float cm = -1e30f;
                    #pragma unroll
                    for (int n8 = 0; n8 < 8; n8++) {
                        cm = fmaxf(cm, S[mt][n8][half * 2 + 0]);
                        cm = fmaxf(cm, S[mt][n8][half * 2 + 1]);
                    }
                    cm = fmaxf(cm, __shfl_xor_sync(0xffffffffu, cm, 1));
                    cm = fmaxf(cm, __shfl_xor_sync(0xffffffffu, cm, 2));
                    float mn = fmaxf(mS[mt][half], cm);
                    float corr = __expf(mS[mt][half] - mn);
                    float rs = 0.f;
                    #pragma unroll
                    for (int n8 = 0; n8 < 8; n8++) {
                        float p0 = __expf(S[mt][n8][half * 2 + 0] - mn);
                        float p1 = __expf(S[mt][n8][half * 2 + 1] - mn);
                        S[mt][n8][half * 2 + 0] = p0;
                        S[mt][n8][half * 2 + 1] = p1;
                        rs += p0 + p1;
                    }
                    rs += __shfl_xor_sync(0xffffffffu, rs, 1);
                    rs += __shfl_xor_sync(0xffffffffu, rs, 2);
                    lS[mt][half] = lS[mt][half] * corr + rs;
                    mS[mt][half] = mn;
                    #pragma unroll
                    for (int n8 = 0; n8 < 8; n8++) {
                        O[mt][n8][half * 2 + 0] *= corr;
                        O[mt][n8][half * 2 + 1] *= corr;
                    }
                }
            }

            #pragma unroll
            for (int kb = 0; kb < 4; kb++) {
                uint32_t ph[2][4];
                #pragma unroll
                for (int mt = 0; mt < 2; mt++) {
                    #pragma unroll
                    for (int i = 0; i < 4; i++) {
                        int j = 2 * kb + (i >> 1);
                        ph[mt][i] = pack_h2(S[mt][j][(i & 1) * 2 + 0],
                                            S[mt][j][(i & 1) * 2 + 1]);
                    }
                }
                uint32_t vf[4][4];
                #pragma unroll
                for (int np = 0; np < 4; np++) {
                    uint32_t row = c0 + kb * 16 + (lane & 15);
                    uint32_t ch = np * 2 + (lane >> 4);
                    ldsm4t(vf[np], sV + swz(row, ch));
                }
                #pragma unroll
                for (int mt = 0; mt < 2; mt++)
                    #pragma unroll
                    for (int n8 = 0; n8 < 8; n8++)
                        mma_fp(O[mt][n8], ph[mt], &vf[n8 >> 1][(n8 & 1) * 2]);
            }
        }
    }

    #pragma unroll
    for (int mt = 0; mt < 2; mt++) {
        #pragma unroll
        for (int half = 0; half < 2; half++) {
            float inv = 1.f / lS[mt][half];
            int row = warpM + mt * 16 + (lane >> 2) + half * 8;
            size_t base = (size_t)(b * SEQ + w * WIN + row) * DIM + h * HD;
            #pragma unroll
            for (int n8 = 0; n8 < 8; n8++) {
                int col = n8 * 8 + (lane & 3) * 2;
                *(uint32_t*)(of + base + col) =
                    pack_h2(O[mt][n8][half * 2 + 0] * inv,
                            O[mt][n8][half * 2 + 1] * inv);
            }
        }
    }
}

// ---------------- host orchestration ---------------------------------------
extern "C" void kernel_launch(void* const* d_in, const int* in_sizes, int n_in,
                              void* d_out, int out_size) {
    const float* x      = (const float*)d_in[0];
    const float* t_emb  = (const float*)d_in[1];
    const float* ln1_g  = (const float*)d_in[2];
    const float* ln1_b  = (const float*)d_in[3];
    const float* qkv_w  = (const float*)d_in[4];
    const float* qkv_b  = (const float*)d_in[5];
    const float* proj_w = (const float*)d_in[6];
    const float* proj_b = (const float*)d_in[7];
    const float* ln2_g  = (const float*)d_in[8];
    const float* ln2_b  = (const float*)d_in[9];
    const float* mlp_w1 = (const float*)d_in[10];
    const float* mlp_b1 = (const float*)d_in[11];
    const float* mlp_w2 = (const float*)d_in[12];
    const float* mlp_b2 = (const float*)d_in[13];
    const float* time_w = (const float*)d_in[14];
    const float* time_b = (const float*)d_in[15];
    float* out = (float*)d_out;

    void* p;
    float* y;
    __half *xf, *af, *ff, *q, *kh, *kl, *v;
    __half *wq, *wp, *w1, *w2;
    cudaGetSymbolAddress(&p, g_y);    y   = (float*)p;
    cudaGetSymbolAddress(&p, g_xf);   xf  = (__half*)p;
    cudaGetSymbolAddress(&p, g_af);   af  = (__half*)p;
    cudaGetSymbolAddress(&p, g_ff);   ff  = (__half*)p;
    cudaGetSymbolAddress(&p, g_q);    q   = (__half*)p;
    cudaGetSymbolAddress(&p, g_kh);   kh  = (__half*)p;
    cudaGetSymbolAddress(&p, g_kl);   kl  = (__half*)p;
    cudaGetSymbolAddress(&p, g_v);    v   = (__half*)p;
    cudaGetSymbolAddress(&p, g_wq);   wq  = (__half*)p;
    cudaGetSymbolAddress(&p, g_wp);   wp  = (__half*)p;
    cudaGetSymbolAddress(&p, g_w1);   w1  = (__half*)p;
    cudaGetSymbolAddress(&p, g_w2);   w2  = (__half*)p;

    const int gemm_smem = 3 * STG;
    cudaFuncSetAttribute(mma_gemm<0>, cudaFuncAttributeMaxDynamicSharedMemorySize, gemm_smem);
    cudaFuncSetAttribute(mma_gemm<1>, cudaFuncAttributeMaxDynamicSharedMemorySize, gemm_smem);
    cudaFuncSetAttribute(mma_gemm<2>, cudaFuncAttributeMaxDynamicSharedMemorySize, gemm_smem);
    cudaFuncSetAttribute(mma_gemm<3>, cudaFuncAttributeMaxDynamicSharedMemorySize, gemm_smem);
    const int attn_smem = 65536;
    cudaFuncSetAttribute(attn_mma_kernel, cudaFuncAttributeMaxDynamicSharedMemorySize, attn_smem);

    wprep_kernel<<<dim3(1536 / 32, 512 / 32), dim3(32, 8)>>>(qkv_w,  wq, 512, 1536);
    wprep_kernel<<<dim3(512 / 32,  512 / 32), dim3(32, 8)>>>(proj_w, wp, 512, 512);
    wprep_kernel<<<dim3(2048 / 32, 512 / 32), dim3(32, 8)>>>(mlp_w1, w1, 512, 2048);
    wprep_kernel<<<dim3(512 / 32, 2048 / 32), dim3(32, 8)>>>(mlp_w2, w2, 2048, 512);
    time_mlp_kernel<<<dim3(2 * DIM / 256, B_), 256>>>(t_emb, time_w, time_b);
    ln_kernel<1><<<NTOK / 8, 256>>>(x, ln1_g, ln1_b, xf);
    mma_gemm<3><<<dim3(12, NTOK / 128), 256, gemm_smem>>>(
        xf, wq, qkv_b, nullptr, nullptr, q, kh, kl, v, 512, 1536);
    attn_mma_kernel<<<dim3(NW, HEADS, B_), 128, attn_smem>>>(q, kh, kl, v, af);
    mma_gemm<1><<<dim3(4, NTOK / 128), 256, gemm_smem>>>(
        af, wp, proj_b, x, y, nullptr, nullptr, nullptr, nullptr, 512, 512);
    ln_kernel<0><<<NTOK / 8, 256>>>(y, ln2_g, ln2_b, xf);
    mma_gemm<2><<<dim3(16, NTOK / 128), 256, gemm_smem>>>(
        xf, w1, mlp_b1, nullptr, nullptr, ff, nullptr, nullptr, nullptr, 512, 2048);
    mma_gemm<1><<<dim3(4, NTOK / 128), 256, gemm_smem>>>(
        ff, w2, mlp_b2, y, out, nullptr, nullptr, nullptr, nullptr, 2048, 512);
}